// round 8
// baseline (speedup 1.0000x reference)
#include <cuda_runtime.h>
#include <cstdint>
#include <cstddef>

#define NE 1000000
#define NN 50000
#define NTG 31250                      // 32-edge groups (NE divisible by 32)
#define PGRID 296
#define WS (PGRID * 8)                 // total warps = tile stride

// node projections stored COLUMN-PERMUTED: logical feature c lives at
// pos(c) = (nt>>1)*16 + tig*4 + (nt&1)*2 + b   where c = 8*nt + 2*tig + b.
__device__ float g_xs[(size_t)NN * 64];
__device__ float g_xt[(size_t)NN * 64];

__device__ __forceinline__ uint32_t f2tf(float f) {
    uint32_t r;
    asm("cvt.rna.tf32.f32 %0, %1;" : "=r"(r) : "f"(f));
    return r;
}

__device__ __forceinline__ uint32_t smem_u32(const void* p) {
    uint32_t a;
    asm("{ .reg .u64 t; cvta.to.shared.u64 t, %1; cvt.u32.u64 %0, t; }" : "=r"(a) : "l"(p));
    return a;
}

__device__ __forceinline__ void mma8(float c[4],
                                     uint32_t a0, uint32_t a1, uint32_t a2, uint32_t a3,
                                     uint32_t b0, uint32_t b1) {
    asm volatile(
        "mma.sync.aligned.m16n8k8.row.col.f32.tf32.tf32.f32 "
        "{%0,%1,%2,%3}, {%4,%5,%6,%7}, {%8,%9}, {%10,%11,%12,%13};\n"
        : "=f"(c[0]), "=f"(c[1]), "=f"(c[2]), "=f"(c[3])
        : "r"(a0), "r"(a1), "r"(a2), "r"(a3), "r"(b0), "r"(b1),
          "f"(c[0]), "f"(c[1]), "f"(c[2]), "f"(c[3]));
}

// jax.nn.gelu approximate: gelu(v) = v * sigmoid(2u), u = sqrt(2/pi)(v+0.044715v^3)
__device__ __forceinline__ float gelu_tanh(float v) {
    float v3 = v * v * v;
    float m2u = -1.5957691216057308f * v - 0.07135481627260025f * v3;  // -2u
    float e = __expf(m2u);
    return __fdividef(v, 1.0f + e);
}

// ---------------------------------------------------------------------------
// Kernel 1: node projections  XS = X@Ws^T + (bs+be),  XT = X@Wt^T + bt
// (output written in pos(c)-permuted column order)
// ---------------------------------------------------------------------------
__global__ __launch_bounds__(256)
void node_proj_kernel(const float* __restrict__ x,
                      const float* __restrict__ Ws, const float* __restrict__ bs,
                      const float* __restrict__ Wt, const float* __restrict__ bt,
                      const float* __restrict__ be) {
    extern __shared__ uint32_t sm1[];
    uint32_t* sX = sm1;                  // 128 x 132
    uint32_t* sW = sm1 + 128 * 132;      // 64 x 132

    const int tid = threadIdx.x;
    const int warp = tid >> 5, lane = tid & 31, g = lane >> 2, tig = lane & 3;
    const int m0 = blockIdx.x * 128;

#pragma unroll
    for (int i = 0; i < 16; i++) {
        int idx = i * 256 + tid;
        int r = idx >> 5, c4 = (idx & 31) * 4;
        float4 v = make_float4(0.f, 0.f, 0.f, 0.f);
        if (m0 + r < NN) v = *(const float4*)(x + (size_t)(m0 + r) * 128 + c4);
        uint32_t* d = sX + r * 132 + c4;
        d[0] = f2tf(v.x); d[1] = f2tf(v.y); d[2] = f2tf(v.z); d[3] = f2tf(v.w);
    }

    const int lr0 = warp * 16 + g;
    const uint32_t* A0 = sX + lr0 * 132;
    const uint32_t* A1 = A0 + 8 * 132;
    const int gr0 = m0 + lr0;

    for (int table = 0; table < 2; table++) {
        const float* W = table ? Wt : Ws;
        __syncthreads();
#pragma unroll
        for (int i = 0; i < 8; i++) {
            int idx = i * 256 + tid;
            int r = idx >> 5, c4 = (idx & 31) * 4;
            float4 v = *(const float4*)(W + r * 128 + c4);
            uint32_t* d = sW + r * 132 + c4;
            d[0] = f2tf(v.x); d[1] = f2tf(v.y); d[2] = f2tf(v.z); d[3] = f2tf(v.w);
        }
        __syncthreads();

        float C[8][4];
#pragma unroll
        for (int nt = 0; nt < 8; nt++) { C[nt][0] = C[nt][1] = C[nt][2] = C[nt][3] = 0.f; }

#pragma unroll
        for (int kt = 0; kt < 16; kt++) {
            uint32_t a0 = A0[kt * 8 + tig], a1 = A1[kt * 8 + tig];
            uint32_t a2 = A0[kt * 8 + tig + 4], a3 = A1[kt * 8 + tig + 4];
#pragma unroll
            for (int nt = 0; nt < 8; nt++) {
                const uint32_t* br = sW + (nt * 8 + g) * 132 + kt * 8;
                mma8(C[nt], a0, a1, a2, a3, br[tig], br[tig + 4]);
            }
        }

        float* dst = table ? g_xt : g_xs;
#pragma unroll
        for (int nt = 0; nt < 8; nt++) {
            int c = nt * 8 + 2 * tig;                                  // logical col
            int pos = (nt >> 1) * 16 + tig * 4 + (nt & 1) * 2;         // permuted slot
            float bias0, bias1;
            if (table == 0) { bias0 = bs[c] + be[c]; bias1 = bs[c + 1] + be[c + 1]; }
            else            { bias0 = bt[c];         bias1 = bt[c + 1]; }
            if (gr0 < NN) {
                float2 v = make_float2(C[nt][0] + bias0, C[nt][1] + bias1);
                *(float2*)(dst + (size_t)gr0 * 64 + pos) = v;
            }
            if (gr0 + 8 < NN) {
                float2 v = make_float2(C[nt][2] + bias0, C[nt][3] + bias1);
                *(float2*)(dst + (size_t)(gr0 + 8) * 64 + pos) = v;
            }
        }
    }
}

// ---------------------------------------------------------------------------
// Kernel 2: fused edge MLP — barrier-free per-warp pipeline, v2.
// Weights stored PLAIN (k-slot = logical col) so b-pairs at 8kt+2tig align
// with adjacent logical cols: stage-1 A = LDS.64 of raw EA; stage-2 A for
// m-tile 0 comes straight from registers (post-gelu C reuse), m-tile 1 via
// same-lane smem round trip. Gathers use __ldcg (L2-direct).
// W1 rows permuted (rp = pos^{-1}) for contiguous STG.128 epilogue.
// ---------------------------------------------------------------------------
__global__ __launch_bounds__(256, 2)
void edge_mlp_kernel(const float* __restrict__ ea,
                     const int* __restrict__ eidx,
                     const float* __restrict__ We,
                     const float* __restrict__ W1,
                     const float* __restrict__ b1,
                     float* __restrict__ out) {
    extern __shared__ uint32_t sm2[];
    uint32_t* sEA = sm2;                     // 256 x 68 (raw f32 EA; rows 16..31/warp reused for H)
    uint32_t* sWe = sm2 + 256 * 68;          // 64 x 72 plain
    uint32_t* sW1 = sWe + 64 * 72;           // 64 x 72 plain cols + permuted rows
    int* sSrc = (int*)(sW1 + 64 * 72);       // 256
    int* sTgt = sSrc + 256;                  // 256
    float* sB1 = (float*)(sTgt + 256);       // 64

    const int tid = threadIdx.x;
    const int warp = tid >> 5, lane = tid & 31, g = lane >> 2, tig = lane & 3;

    // ---- stage weights ONCE (plain k layout; W1 rows permuted) ----
#pragma unroll
    for (int i = 0; i < 8; i++) {
        int idx = i * 256 + tid;             // 2048 float4 over both tables
        int table = idx >> 10;
        int rem = idx & 1023;
        int r = rem >> 4, c4 = (rem & 15) * 4;
        const float* W = table ? W1 : We;
        uint32_t* dst = table ? sW1 : sWe;
        // W1: physical row rp = pos^{-1}(r): rp3<-r1, rp2<-r3, rp1<-r2; bits 5,4,0 fixed
        int rp = table
               ? ((r & 0x31) | ((r & 0x2) << 2) | ((r & 0x8) >> 1) | ((r & 0x4) >> 1))
               : r;
        float4 v = *(const float4*)(W + r * 64 + c4);
        uint4 t;
        t.x = f2tf(v.x); t.y = f2tf(v.y); t.z = f2tf(v.z); t.w = f2tf(v.w);
        *(uint4*)(dst + rp * 72 + c4) = t;
    }
    if (tid < 64) sB1[tid] = b1[tid];
    __syncthreads();   // weights/bias visible; after this, warps are independent

    const int rb = warp * 32 + g;            // row slots: rb, rb+8, rb+16, rb+24
    uint32_t* A0 = sEA + rb * 68;
    uint32_t* A1 = A0 + 8 * 68;
    uint32_t* A2 = A0 + 16 * 68;
    uint32_t* A3 = A0 + 24 * 68;

    const uint32_t eaRowAddr = smem_u32(sEA) + (uint32_t)(warp * 32) * 68 * 4;
    const int wg0 = blockIdx.x * 8 + warp;   // global warp id

    float4 bia[4];
#pragma unroll
    for (int i = 0; i < 4; i++) bia[i] = *(const float4*)(sB1 + i * 16 + tig * 4);

    // ---- prologue: prefetch EA for first tile ----
    if (wg0 < NTG) {
        const float* gsrc = ea + (size_t)wg0 * 32 * 64;
#pragma unroll
        for (int i = 0; i < 16; i++) {
            int idx = i * 32 + lane;
            int r = idx >> 4, c4 = (idx & 15) << 2;
            uint32_t dst = eaRowAddr + (uint32_t)(r * 68 + c4) * 4;
            asm volatile("cp.async.cg.shared.global [%0], [%1], 16;"
                         :: "r"(dst), "l"(gsrc + r * 64 + c4) : "memory");
        }
    }
    asm volatile("cp.async.commit_group;" ::: "memory");

    for (int tile = wg0; tile < NTG; tile += WS) {
        const long long e0 = (long long)tile * 32;

        // indices for this warp's 32 edges (int32; clamp defensively)
        {
            int vs = eidx[e0 + lane];
            int vt = eidx[NE + e0 + lane];
            sSrc[warp * 32 + lane] = min(max(vs, 0), NN - 1);
            sTgt[warp * 32 + lane] = min(max(vt, 0), NN - 1);
        }
        asm volatile("cp.async.wait_group 0;" ::: "memory");
        __syncwarp();   // EA copies + index STS visible across the warp

        // ---- stage 1: H = EA @ We^T  (A = LDS.64 raw f32 -> tf32) ----
        float C[2][8][4];
#pragma unroll
        for (int s = 0; s < 2; s++)
#pragma unroll
            for (int nt = 0; nt < 8; nt++) { C[s][nt][0] = C[s][nt][1] = C[s][nt][2] = C[s][nt][3] = 0.f; }

#pragma unroll
        for (int kt = 0; kt < 8; kt++) {
            const int ko = kt * 8 + 2 * tig;
            uint2 e0v = *(const uint2*)(A0 + ko);
            uint2 e1v = *(const uint2*)(A1 + ko);
            uint2 e2v = *(const uint2*)(A2 + ko);
            uint2 e3v = *(const uint2*)(A3 + ko);
            uint32_t a00 = f2tf(__uint_as_float(e0v.x)), a02 = f2tf(__uint_as_float(e0v.y));
            uint32_t a01 = f2tf(__uint_as_float(e1v.x)), a03 = f2tf(__uint_as_float(e1v.y));
            uint32_t a10 = f2tf(__uint_as_float(e2v.x)), a12 = f2tf(__uint_as_float(e2v.y));
            uint32_t a11 = f2tf(__uint_as_float(e3v.x)), a13 = f2tf(__uint_as_float(e3v.y));
#pragma unroll
            for (int nt = 0; nt < 8; nt++) {
                uint2 b = *(const uint2*)(sWe + (nt * 8 + g) * 72 + ko);
                mma8(C[0][nt], a00, a01, a02, a03, b.x, b.y);
                mma8(C[1][nt], a10, a11, a12, a13, b.x, b.y);
            }
        }

        // ---- gather (__ldcg, permuted tables) + GELU ----
        // s=0,1: H stays in C[0] registers (reinterpreted as tf32 bits).
        // s=2,3: H stored to own smem rows at logical cols (same-lane round trip).
#pragma unroll
        for (int s = 0; s < 4; s++) {
            const int row = rb + 8 * s;
            const int h = s >> 1, pb = (s & 1) * 2;
            const float* xs = g_xs + (size_t)sSrc[row] * 64 + tig * 4;
            const float* xt = g_xt + (size_t)sTgt[row] * 64 + tig * 4;
#pragma unroll
            for (int i = 0; i < 4; i++) {
                float4 p = __ldcg((const float4*)(xs + i * 16));
                float4 q = __ldcg((const float4*)(xt + i * 16));
                float v0 = C[h][2 * i + 0][pb + 0] + p.x + q.x;
                float v1 = C[h][2 * i + 0][pb + 1] + p.y + q.y;
                float v2 = C[h][2 * i + 1][pb + 0] + p.z + q.z;
                float v3 = C[h][2 * i + 1][pb + 1] + p.w + q.w;
                uint32_t h0 = f2tf(gelu_tanh(v0)), h1 = f2tf(gelu_tanh(v1));
                uint32_t h2 = f2tf(gelu_tanh(v2)), h3 = f2tf(gelu_tanh(v3));
                if (s < 2) {
                    C[0][2 * i + 0][pb + 0] = __uint_as_float(h0);
                    C[0][2 * i + 0][pb + 1] = __uint_as_float(h1);
                    C[0][2 * i + 1][pb + 0] = __uint_as_float(h2);
                    C[0][2 * i + 1][pb + 1] = __uint_as_float(h3);
                } else {
                    uint2 w0; w0.x = h0; w0.y = h1;
                    uint2 w1; w1.x = h2; w1.y = h3;
                    *(uint2*)(sEA + row * 68 + 8 * (2 * i + 0) + 2 * tig) = w0;
                    *(uint2*)(sEA + row * 68 + 8 * (2 * i + 1) + 2 * tig) = w1;
                }
            }
        }
        // no sync needed: m-tile1 smem H is re-read by the SAME lane that wrote it

        // ---- stage 2: OUT = H @ W1p^T (N permuted; A mtile0 from regs) ----
        float D[2][8][4];
#pragma unroll
        for (int s = 0; s < 2; s++)
#pragma unroll
            for (int nt = 0; nt < 8; nt++) { D[s][nt][0] = D[s][nt][1] = D[s][nt][2] = D[s][nt][3] = 0.f; }

#pragma unroll
        for (int kt = 0; kt < 8; kt++) {
            const int ko = kt * 8 + 2 * tig;
            // mtile0: rows g (C[0][kt][0,1]) and g+8 (C[0][kt][2,3])
            uint32_t a00 = __float_as_uint(C[0][kt][0]);
            uint32_t a02 = __float_as_uint(C[0][kt][1]);
            uint32_t a01 = __float_as_uint(C[0][kt][2]);
            uint32_t a03 = __float_as_uint(C[0][kt][3]);
            // mtile1: rows g+16, g+24 via same-lane smem
            uint2 m0 = *(const uint2*)(A2 + ko);
            uint2 m1 = *(const uint2*)(A3 + ko);
#pragma unroll
            for (int nt = 0; nt < 8; nt++) {
                uint2 b = *(const uint2*)(sW1 + (nt * 8 + g) * 72 + ko);
                mma8(D[0][nt], a00, a01, a02, a03, b.x, b.y);
                mma8(D[1][nt], m0.x, m1.x, m0.y, m1.y, b.x, b.y);
            }
        }

        // ---- prefetch next tile's EA (rows free after stage-2 A loads) ----
        if (tile + WS < NTG) {
            const float* gsrc = ea + (size_t)(tile + WS) * 32 * 64;
#pragma unroll
            for (int i = 0; i < 16; i++) {
                int idx = i * 32 + lane;
                int r = idx >> 4, c4 = (idx & 15) << 2;
                uint32_t dst = eaRowAddr + (uint32_t)(r * 68 + c4) * 4;
                asm volatile("cp.async.cg.shared.global [%0], [%1], 16;"
                             :: "r"(dst), "l"(gsrc + r * 64 + c4) : "memory");
            }
        }
        asm volatile("cp.async.commit_group;" ::: "memory");

        // ---- epilogue: +b1, STG.128 at logical cols i*16 + tig*4 ----
#pragma unroll
        for (int s = 0; s < 4; s++) {
            const int h = s >> 1, pb = (s & 1) * 2;
            float* orow = out + (size_t)(e0 + g + 8 * s) * 64 + tig * 4;
#pragma unroll
            for (int i = 0; i < 4; i++) {
                float4 v;
                v.x = D[h][2 * i + 0][pb + 0] + bia[i].x;
                v.y = D[h][2 * i + 0][pb + 1] + bia[i].y;
                v.z = D[h][2 * i + 1][pb + 0] + bia[i].z;
                v.w = D[h][2 * i + 1][pb + 1] + bia[i].w;
                *(float4*)(orow + i * 16) = v;
            }
        }
    }
}

extern "C" void kernel_launch(void* const* d_in, const int* in_sizes, int n_in,
                              void* d_out, int out_size) {
    const float* x   = (const float*)d_in[0];
    const int*   ei  = (const int*)d_in[1];     // int32 (JAX default x64-disabled)
    const float* ea  = (const float*)d_in[2];
    const float* We  = (const float*)d_in[3];
    const float* be  = (const float*)d_in[4];
    const float* Ws  = (const float*)d_in[5];
    const float* bs  = (const float*)d_in[6];
    const float* Wt  = (const float*)d_in[7];
    const float* bt  = (const float*)d_in[8];
    const float* W1  = (const float*)d_in[9];
    const float* b1  = (const float*)d_in[10];
    float* out = (float*)d_out;

    const size_t smem1 = (size_t)(128 * 132 + 64 * 132) * 4;                   // ~99 KB
    const size_t smem2 = (size_t)(256 * 68 + 2 * 64 * 72 + 512 + 64 + 16) * 4; // ~109 KB
    cudaFuncSetAttribute(node_proj_kernel, cudaFuncAttributeMaxDynamicSharedMemorySize, (int)smem1);
    cudaFuncSetAttribute(edge_mlp_kernel,  cudaFuncAttributeMaxDynamicSharedMemorySize, (int)smem2);

    node_proj_kernel<<<(NN + 127) / 128, 256, smem1>>>(x, Ws, bs, Wt, bt, be);
    edge_mlp_kernel<<<PGRID, 256, smem2>>>(ea, ei, We, W1, b1, out);
}

// round 9
// speedup vs baseline: 1.0299x; 1.0299x over previous
#include <cuda_runtime.h>
#include <cstdint>
#include <cstddef>

#define NE 1000000
#define NN 50000
#define NTG 31250                      // 32-edge groups (NE divisible by 32)
#define PGRID 296
#define WS (PGRID * 8)                 // total warps = tile stride

// node projections stored COLUMN-PERMUTED: logical feature c lives at
// pos(c) = (nt>>1)*16 + tig*4 + (nt&1)*2 + b   where c = 8*nt + 2*tig + b.
__device__ float g_xs[(size_t)NN * 64];
__device__ float g_xt[(size_t)NN * 64];

__device__ __forceinline__ uint32_t f2tf(float f) {
    uint32_t r;
    asm("cvt.rna.tf32.f32 %0, %1;" : "=r"(r) : "f"(f));
    return r;
}

__device__ __forceinline__ uint32_t smem_u32(const void* p) {
    uint32_t a;
    asm("{ .reg .u64 t; cvta.to.shared.u64 t, %1; cvt.u32.u64 %0, t; }" : "=r"(a) : "l"(p));
    return a;
}

__device__ __forceinline__ void mma8(float c[4],
                                     uint32_t a0, uint32_t a1, uint32_t a2, uint32_t a3,
                                     uint32_t b0, uint32_t b1) {
    asm volatile(
        "mma.sync.aligned.m16n8k8.row.col.f32.tf32.tf32.f32 "
        "{%0,%1,%2,%3}, {%4,%5,%6,%7}, {%8,%9}, {%10,%11,%12,%13};\n"
        : "=f"(c[0]), "=f"(c[1]), "=f"(c[2]), "=f"(c[3])
        : "r"(a0), "r"(a1), "r"(a2), "r"(a3), "r"(b0), "r"(b1),
          "f"(c[0]), "f"(c[1]), "f"(c[2]), "f"(c[3]));
}

// jax.nn.gelu approximate: gelu(v) = v * sigmoid(2u), u = sqrt(2/pi)(v+0.044715v^3)
__device__ __forceinline__ float gelu_tanh(float v) {
    float v3 = v * v * v;
    float m2u = -1.5957691216057308f * v - 0.07135481627260025f * v3;  // -2u
    float e = __expf(m2u);
    return __fdividef(v, 1.0f + e);
}

// ---------------------------------------------------------------------------
// Kernel 1: node projections  XS = X@Ws^T + (bs+be),  XT = X@Wt^T + bt
// (output written in pos(c)-permuted column order)
// ---------------------------------------------------------------------------
__global__ __launch_bounds__(256)
void node_proj_kernel(const float* __restrict__ x,
                      const float* __restrict__ Ws, const float* __restrict__ bs,
                      const float* __restrict__ Wt, const float* __restrict__ bt,
                      const float* __restrict__ be) {
    extern __shared__ uint32_t sm1[];
    uint32_t* sX = sm1;                  // 128 x 132
    uint32_t* sW = sm1 + 128 * 132;      // 64 x 132

    const int tid = threadIdx.x;
    const int warp = tid >> 5, lane = tid & 31, g = lane >> 2, tig = lane & 3;
    const int m0 = blockIdx.x * 128;

#pragma unroll
    for (int i = 0; i < 16; i++) {
        int idx = i * 256 + tid;
        int r = idx >> 5, c4 = (idx & 31) * 4;
        float4 v = make_float4(0.f, 0.f, 0.f, 0.f);
        if (m0 + r < NN) v = *(const float4*)(x + (size_t)(m0 + r) * 128 + c4);
        uint32_t* d = sX + r * 132 + c4;
        d[0] = f2tf(v.x); d[1] = f2tf(v.y); d[2] = f2tf(v.z); d[3] = f2tf(v.w);
    }

    const int lr0 = warp * 16 + g;
    const uint32_t* A0 = sX + lr0 * 132;
    const uint32_t* A1 = A0 + 8 * 132;
    const int gr0 = m0 + lr0;

    for (int table = 0; table < 2; table++) {
        const float* W = table ? Wt : Ws;
        __syncthreads();
#pragma unroll
        for (int i = 0; i < 8; i++) {
            int idx = i * 256 + tid;
            int r = idx >> 5, c4 = (idx & 31) * 4;
            float4 v = *(const float4*)(W + r * 128 + c4);
            uint32_t* d = sW + r * 132 + c4;
            d[0] = f2tf(v.x); d[1] = f2tf(v.y); d[2] = f2tf(v.z); d[3] = f2tf(v.w);
        }
        __syncthreads();

        float C[8][4];
#pragma unroll
        for (int nt = 0; nt < 8; nt++) { C[nt][0] = C[nt][1] = C[nt][2] = C[nt][3] = 0.f; }

#pragma unroll
        for (int kt = 0; kt < 16; kt++) {
            uint32_t a0 = A0[kt * 8 + tig], a1 = A1[kt * 8 + tig];
            uint32_t a2 = A0[kt * 8 + tig + 4], a3 = A1[kt * 8 + tig + 4];
#pragma unroll
            for (int nt = 0; nt < 8; nt++) {
                const uint32_t* br = sW + (nt * 8 + g) * 132 + kt * 8;
                mma8(C[nt], a0, a1, a2, a3, br[tig], br[tig + 4]);
            }
        }

        float* dst = table ? g_xt : g_xs;
#pragma unroll
        for (int nt = 0; nt < 8; nt++) {
            int c = nt * 8 + 2 * tig;                                  // logical col
            int pos = (nt >> 1) * 16 + tig * 4 + (nt & 1) * 2;         // permuted slot
            float bias0, bias1;
            if (table == 0) { bias0 = bs[c] + be[c]; bias1 = bs[c + 1] + be[c + 1]; }
            else            { bias0 = bt[c];         bias1 = bt[c + 1]; }
            if (gr0 < NN) {
                float2 v = make_float2(C[nt][0] + bias0, C[nt][1] + bias1);
                *(float2*)(dst + (size_t)gr0 * 64 + pos) = v;
            }
            if (gr0 + 8 < NN) {
                float2 v = make_float2(C[nt][2] + bias0, C[nt][3] + bias1);
                *(float2*)(dst + (size_t)(gr0 + 8) * 64 + pos) = v;
            }
        }
    }
}

// ---------------------------------------------------------------------------
// Kernel 2: fused edge MLP — barrier-free per-warp pipeline (R7 structure).
// Each warp owns 32 sEA rows + 32 indices; tiles are 32 edges per warp.
// EA staged raw f32 via cp.async (depth-1 prefetch); tf32 cvt at A-fragment
// consumption. Weights staged once per CTA (col pair-interleave; W1 row-perm).
// Gathers use __ldcg (L2-direct, no L1 allocate).
// ---------------------------------------------------------------------------
__global__ __launch_bounds__(256, 2)
void edge_mlp_kernel(const float* __restrict__ ea,
                     const int* __restrict__ eidx,
                     const float* __restrict__ We,
                     const float* __restrict__ W1,
                     const float* __restrict__ b1,
                     float* __restrict__ out) {
    extern __shared__ uint32_t sm2[];
    uint32_t* sEA = sm2;                     // 256 x 68 (raw f32 EA, then tf32 H)
    uint32_t* sWe = sm2 + 256 * 68;          // 64 x 72 col-interleaved
    uint32_t* sW1 = sWe + 64 * 72;           // 64 x 72 col-interleaved + row-permuted
    int* sSrc = (int*)(sW1 + 64 * 72);       // 256
    int* sTgt = sSrc + 256;                  // 256
    float* sB1 = (float*)(sTgt + 256);       // 64

    const int tid = threadIdx.x;
    const int warp = tid >> 5, lane = tid & 31, g = lane >> 2, tig = lane & 3;

    // ---- stage weights ONCE (col pair-interleave; W1 also row-permuted) ----
#pragma unroll
    for (int i = 0; i < 8; i++) {
        int idx = i * 256 + tid;             // 2048 float4 over both tables
        int table = idx >> 10;
        int rem = idx & 1023;
        int r = rem >> 4, c4 = (rem & 15) * 4;
        const float* W = table ? W1 : We;
        uint32_t* dst = table ? sW1 : sWe;
        // W1: physical row rp = pos^{-1}(r): rp3<-r1, rp2<-r3, rp1<-r2; bits 5,4,0 fixed
        int rp = table
               ? ((r & 0x31) | ((r & 0x2) << 2) | ((r & 0x8) >> 1) | ((r & 0x4) >> 1))
               : r;
        float4 v = *(const float4*)(W + r * 64 + c4);
        float vv[4] = {v.x, v.y, v.z, v.w};
#pragma unroll
        for (int m = 0; m < 4; m++) {
            int c = c4 + m;
            int kpos = ((c >> 3) << 3) + (((c & 3) << 1) | ((c >> 2) & 1));
            dst[rp * 72 + kpos] = f2tf(vv[m]);
        }
    }
    if (tid < 64) sB1[tid] = b1[tid];
    __syncthreads();   // weights/bias visible; after this, warps are independent

    const int rb = warp * 32 + g;            // row slots: rb, rb+8, rb+16, rb+24
    uint32_t* A0 = sEA + rb * 68;
    uint32_t* A1 = A0 + 8 * 68;
    uint32_t* A2 = A0 + 16 * 68;
    uint32_t* A3 = A0 + 24 * 68;

    const uint32_t eaRowAddr = smem_u32(sEA) + (uint32_t)(warp * 32) * 68 * 4;
    const int wg0 = blockIdx.x * 8 + warp;   // global warp id

    // ---- prologue: prefetch EA for first tile ----
    if (wg0 < NTG) {
        const float* gsrc = ea + (size_t)wg0 * 32 * 64;
#pragma unroll
        for (int i = 0; i < 16; i++) {
            int idx = i * 32 + lane;
            int r = idx >> 4, c4 = (idx & 15) << 2;
            uint32_t dst = eaRowAddr + (uint32_t)(r * 68 + c4) * 4;
            asm volatile("cp.async.cg.shared.global [%0], [%1], 16;"
                         :: "r"(dst), "l"(gsrc + r * 64 + c4) : "memory");
        }
    }
    asm volatile("cp.async.commit_group;" ::: "memory");

    for (int tile = wg0; tile < NTG; tile += WS) {
        const long long e0 = (long long)tile * 32;

        // indices for this warp's 32 edges (int32; clamp defensively)
        {
            int vs = eidx[e0 + lane];
            int vt = eidx[NE + e0 + lane];
            sSrc[warp * 32 + lane] = min(max(vs, 0), NN - 1);
            sTgt[warp * 32 + lane] = min(max(vt, 0), NN - 1);
        }
        asm volatile("cp.async.wait_group 0;" ::: "memory");
        __syncwarp();   // EA copies + index STS visible across the warp

        // ---- stage 1: H = EA @ We^T  (A raw f32 -> tf32 at consumption) ----
        float C[2][8][4];
#pragma unroll
        for (int s = 0; s < 2; s++)
#pragma unroll
            for (int nt = 0; nt < 8; nt++) { C[s][nt][0] = C[s][nt][1] = C[s][nt][2] = C[s][nt][3] = 0.f; }

#pragma unroll
        for (int kt = 0; kt < 8; kt++) {
            const int ko = kt * 8;
            uint32_t a00 = f2tf(__uint_as_float(A0[ko + tig]));
            uint32_t a01 = f2tf(__uint_as_float(A1[ko + tig]));
            uint32_t a02 = f2tf(__uint_as_float(A0[ko + tig + 4]));
            uint32_t a03 = f2tf(__uint_as_float(A1[ko + tig + 4]));
            uint32_t a10 = f2tf(__uint_as_float(A2[ko + tig]));
            uint32_t a11 = f2tf(__uint_as_float(A3[ko + tig]));
            uint32_t a12 = f2tf(__uint_as_float(A2[ko + tig + 4]));
            uint32_t a13 = f2tf(__uint_as_float(A3[ko + tig + 4]));
#pragma unroll
            for (int nt = 0; nt < 8; nt++) {
                uint2 b = *(const uint2*)(sWe + (nt * 8 + g) * 72 + ko + 2 * tig);
                mma8(C[0][nt], a00, a01, a02, a03, b.x, b.y);
                mma8(C[1][nt], a10, a11, a12, a13, b.x, b.y);
            }
        }

        // ---- gather (__ldcg L2-direct, permuted tables) + GELU -> H to smem ----
#pragma unroll
        for (int s = 0; s < 4; s++) {
            const int row = rb + 8 * s;
            const int h = s >> 1, pb = (s & 1) * 2;
            const float* xs = g_xs + (size_t)sSrc[row] * 64 + tig * 4;
            const float* xt = g_xt + (size_t)sTgt[row] * 64 + tig * 4;
#pragma unroll
            for (int i = 0; i < 4; i++) {
                float4 p = __ldcg((const float4*)(xs + i * 16));
                float4 q = __ldcg((const float4*)(xt + i * 16));
                float v0 = C[h][2 * i + 0][pb + 0] + p.x + q.x;
                float v1 = C[h][2 * i + 0][pb + 1] + p.y + q.y;
                float v2 = C[h][2 * i + 1][pb + 0] + p.z + q.z;
                float v3 = C[h][2 * i + 1][pb + 1] + p.w + q.w;
                uint2 h0, h1;
                h0.x = f2tf(gelu_tanh(v0)); h0.y = f2tf(gelu_tanh(v1));
                h1.x = f2tf(gelu_tanh(v2)); h1.y = f2tf(gelu_tanh(v3));
                *(uint2*)(sEA + row * 68 + 16 * i + 2 * tig) = h0;       // col 8*(2i)
                *(uint2*)(sEA + row * 68 + 16 * i + 8 + 2 * tig) = h1;   // col 8*(2i+1)
            }
        }
        __syncwarp();  // H rows are warp-private

        // ---- stage 2: OUT = H @ W1p^T (N permuted) ----
#pragma unroll
        for (int s = 0; s < 2; s++)
#pragma unroll
            for (int nt = 0; nt < 8; nt++) { C[s][nt][0] = C[s][nt][1] = C[s][nt][2] = C[s][nt][3] = 0.f; }

#pragma unroll
        for (int kt = 0; kt < 8; kt++) {
            const int ko = kt * 8;
            uint32_t a00 = A0[ko + tig], a01 = A1[ko + tig];
            uint32_t a02 = A0[ko + tig + 4], a03 = A1[ko + tig + 4];
            uint32_t a10 = A2[ko + tig], a11 = A3[ko + tig];
            uint32_t a12 = A2[ko + tig + 4], a13 = A3[ko + tig + 4];
#pragma unroll
            for (int nt = 0; nt < 8; nt++) {
                uint2 b = *(const uint2*)(sW1 + (nt * 8 + g) * 72 + ko + 2 * tig);
                mma8(C[0][nt], a00, a01, a02, a03, b.x, b.y);
                mma8(C[1][nt], a10, a11, a12, a13, b.x, b.y);
            }
        }

        // ---- prefetch next tile's EA (rows free after stage-2 A loads) ----
        if (tile + WS < NTG) {
            const float* gsrc = ea + (size_t)(tile + WS) * 32 * 64;
#pragma unroll
            for (int i = 0; i < 16; i++) {
                int idx = i * 32 + lane;
                int r = idx >> 4, c4 = (idx & 15) << 2;
                uint32_t dst = eaRowAddr + (uint32_t)(r * 68 + c4) * 4;
                asm volatile("cp.async.cg.shared.global [%0], [%1], 16;"
                             :: "r"(dst), "l"(gsrc + r * 64 + c4) : "memory");
            }
        }
        asm volatile("cp.async.commit_group;" ::: "memory");

        // ---- epilogue: +b1, STG.128 at logical cols i*16 + tig*4 ----
        float4 bia[4];
#pragma unroll
        for (int i = 0; i < 4; i++) bia[i] = *(const float4*)(sB1 + i * 16 + tig * 4);
#pragma unroll
        for (int s = 0; s < 4; s++) {
            const int h = s >> 1, pb = (s & 1) * 2;
            float* orow = out + (size_t)(e0 + g + 8 * s) * 64 + tig * 4;
#pragma unroll
            for (int i = 0; i < 4; i++) {
                float4 v;
                v.x = C[h][2 * i + 0][pb + 0] + bia[i].x;
                v.y = C[h][2 * i + 0][pb + 1] + bia[i].y;
                v.z = C[h][2 * i + 1][pb + 0] + bia[i].z;
                v.w = C[h][2 * i + 1][pb + 1] + bia[i].w;
                *(float4*)(orow + i * 16) = v;
            }
        }
    }
}

extern "C" void kernel_launch(void* const* d_in, const int* in_sizes, int n_in,
                              void* d_out, int out_size) {
    const float* x   = (const float*)d_in[0];
    const int*   ei  = (const int*)d_in[1];     // int32 (JAX default x64-disabled)
    const float* ea  = (const float*)d_in[2];
    const float* We  = (const float*)d_in[3];
    const float* be  = (const float*)d_in[4];
    const float* Ws  = (const float*)d_in[5];
    const float* bs  = (const float*)d_in[6];
    const float* Wt  = (const float*)d_in[7];
    const float* bt  = (const float*)d_in[8];
    const float* W1  = (const float*)d_in[9];
    const float* b1  = (const float*)d_in[10];
    float* out = (float*)d_out;

    const size_t smem1 = (size_t)(128 * 132 + 64 * 132) * 4;                   // ~99 KB
    const size_t smem2 = (size_t)(256 * 68 + 2 * 64 * 72 + 512 + 64 + 16) * 4; // ~109 KB
    cudaFuncSetAttribute(node_proj_kernel, cudaFuncAttributeMaxDynamicSharedMemorySize, (int)smem1);
    cudaFuncSetAttribute(edge_mlp_kernel,  cudaFuncAttributeMaxDynamicSharedMemorySize, (int)smem2);

    node_proj_kernel<<<(NN + 127) / 128, 256, smem1>>>(x, Ws, bs, Wt, bt, be);
    edge_mlp_kernel<<<PGRID, 256, smem2>>>(ea, ei, We, W1, b1, out);
}

// round 10
// speedup vs baseline: 1.2157x; 1.1803x over previous
#include <cuda_runtime.h>
#include <cstdint>
#include <cstddef>

#define NE 1000000
#define NN 50000
#define NTG 31250                      // 32-edge groups (NE divisible by 32)
#define PGRID 296
#define WS (PGRID * 8)                 // total warps = tile stride

// node projections stored COLUMN-PERMUTED: logical feature c lives at
// pos(c) = (nt>>1)*16 + tig*4 + (nt&1)*2 + b   where c = 8*nt + 2*tig + b.
__device__ float g_xs[(size_t)NN * 64];
__device__ float g_xt[(size_t)NN * 64];

__device__ __forceinline__ uint32_t f2tf(float f) {
    uint32_t r;
    asm("cvt.rna.tf32.f32 %0, %1;" : "=r"(r) : "f"(f));
    return r;
}

__device__ __forceinline__ uint32_t smem_u32(const void* p) {
    uint32_t a;
    asm("{ .reg .u64 t; cvta.to.shared.u64 t, %1; cvt.u32.u64 %0, t; }" : "=r"(a) : "l"(p));
    return a;
}

__device__ __forceinline__ void mma8(float c[4],
                                     uint32_t a0, uint32_t a1, uint32_t a2, uint32_t a3,
                                     uint32_t b0, uint32_t b1) {
    asm volatile(
        "mma.sync.aligned.m16n8k8.row.col.f32.tf32.tf32.f32 "
        "{%0,%1,%2,%3}, {%4,%5,%6,%7}, {%8,%9}, {%10,%11,%12,%13};\n"
        : "=f"(c[0]), "=f"(c[1]), "=f"(c[2]), "=f"(c[3])
        : "r"(a0), "r"(a1), "r"(a2), "r"(a3), "r"(b0), "r"(b1),
          "f"(c[0]), "f"(c[1]), "f"(c[2]), "f"(c[3]));
}

// jax.nn.gelu approximate: gelu(v) = v * sigmoid(2u), u = sqrt(2/pi)(v+0.044715v^3)
__device__ __forceinline__ float gelu_tanh(float v) {
    float v3 = v * v * v;
    float m2u = -1.5957691216057308f * v - 0.07135481627260025f * v3;  // -2u
    float e = __expf(m2u);
    return __fdividef(v, 1.0f + e);
}

// ---------------------------------------------------------------------------
// Kernel 1: node projections, single pass.
// 64 nodes/block, 256 threads (8 warps): warp = (nhalf, mtile) with
// nhalf = warp>>2 selecting Ws (->g_xs, bias bs+be) or Wt (->g_xt, bias bt).
// B tile = [Ws; Wt] stacked (128 rows x 128 cols), one staging + one barrier.
// Output written in pos(c)-permuted column order.
// ---------------------------------------------------------------------------
__global__ __launch_bounds__(256)
void node_proj_kernel(const float* __restrict__ x,
                      const float* __restrict__ Ws, const float* __restrict__ bs,
                      const float* __restrict__ Wt, const float* __restrict__ bt,
                      const float* __restrict__ be) {
    extern __shared__ uint32_t sm1[];
    uint32_t* sX = sm1;                  // 64 x 132
    uint32_t* sW = sm1 + 64 * 132;       // 128 x 132 ([Ws;Wt])

    const int tid = threadIdx.x;
    const int warp = tid >> 5, lane = tid & 31, g = lane >> 2, tig = lane & 3;
    const int m0 = blockIdx.x * 64;

    // stage X tile (zero-fill OOB rows): 64 rows x 32 float4 = 2048 tasks
#pragma unroll
    for (int i = 0; i < 8; i++) {
        int idx = i * 256 + tid;
        int r = idx >> 5, c4 = (idx & 31) * 4;
        float4 v = make_float4(0.f, 0.f, 0.f, 0.f);
        if (m0 + r < NN) v = *(const float4*)(x + (size_t)(m0 + r) * 128 + c4);
        uint32_t* d = sX + r * 132 + c4;
        d[0] = f2tf(v.x); d[1] = f2tf(v.y); d[2] = f2tf(v.z); d[3] = f2tf(v.w);
    }
    // stage both weight tables: 2 x 64 rows x 32 float4 = 4096 tasks
#pragma unroll
    for (int i = 0; i < 16; i++) {
        int idx = i * 256 + tid;
        int table = idx >> 11;
        int rem = idx & 2047;
        int r = rem >> 5, c4 = (rem & 31) * 4;
        const float* W = table ? Wt : Ws;
        float4 v = *(const float4*)(W + r * 128 + c4);
        uint32_t* d = sW + (table * 64 + r) * 132 + c4;
        d[0] = f2tf(v.x); d[1] = f2tf(v.y); d[2] = f2tf(v.z); d[3] = f2tf(v.w);
    }
    __syncthreads();

    const int mt = warp & 3, nh = warp >> 2;
    const int lr0 = mt * 16 + g;
    const uint32_t* A0 = sX + lr0 * 132;
    const uint32_t* A1 = A0 + 8 * 132;
    const uint32_t* Bbase = sW + nh * 64 * 132;
    const int gr0 = m0 + lr0;

    float C[8][4];
#pragma unroll
    for (int nt = 0; nt < 8; nt++) { C[nt][0] = C[nt][1] = C[nt][2] = C[nt][3] = 0.f; }

#pragma unroll
    for (int kt = 0; kt < 16; kt++) {
        uint32_t a0 = A0[kt * 8 + tig], a1 = A1[kt * 8 + tig];
        uint32_t a2 = A0[kt * 8 + tig + 4], a3 = A1[kt * 8 + tig + 4];
#pragma unroll
        for (int nt = 0; nt < 8; nt++) {
            const uint32_t* br = Bbase + (nt * 8 + g) * 132 + kt * 8;
            mma8(C[nt], a0, a1, a2, a3, br[tig], br[tig + 4]);
        }
    }

    float* dst = nh ? g_xt : g_xs;
#pragma unroll
    for (int nt = 0; nt < 8; nt++) {
        int c = nt * 8 + 2 * tig;                                  // logical col
        int pos = (nt >> 1) * 16 + tig * 4 + (nt & 1) * 2;         // permuted slot
        float bias0, bias1;
        if (nh == 0) { bias0 = bs[c] + be[c]; bias1 = bs[c + 1] + be[c + 1]; }
        else         { bias0 = bt[c];         bias1 = bt[c + 1]; }
        if (gr0 < NN) {
            float2 v = make_float2(C[nt][0] + bias0, C[nt][1] + bias1);
            *(float2*)(dst + (size_t)gr0 * 64 + pos) = v;
        }
        if (gr0 + 8 < NN) {
            float2 v = make_float2(C[nt][2] + bias0, C[nt][3] + bias1);
            *(float2*)(dst + (size_t)(gr0 + 8) * 64 + pos) = v;
        }
    }
}

// ---------------------------------------------------------------------------
// Kernel 2: fused edge MLP — barrier-free per-warp pipeline (R7 structure).
// Each warp owns 32 sEA rows + 32 indices; tiles are 32 edges per warp.
// EA staged raw f32 via cp.async (depth-1 prefetch); tf32 cvt at A-fragment
// consumption. Weights staged once per CTA (col pair-interleave; W1 row-perm).
// Edge indices prefetched one tile ahead in registers.
// Gathers are plain L1-cached loads (in-degree ~20 -> real L1 reuse).
// ---------------------------------------------------------------------------
__global__ __launch_bounds__(256, 2)
void edge_mlp_kernel(const float* __restrict__ ea,
                     const int* __restrict__ eidx,
                     const float* __restrict__ We,
                     const float* __restrict__ W1,
                     const float* __restrict__ b1,
                     float* __restrict__ out) {
    extern __shared__ uint32_t sm2[];
    uint32_t* sEA = sm2;                     // 256 x 68 (raw f32 EA, then tf32 H)
    uint32_t* sWe = sm2 + 256 * 68;          // 64 x 72 col-interleaved
    uint32_t* sW1 = sWe + 64 * 72;           // 64 x 72 col-interleaved + row-permuted
    int* sSrc = (int*)(sW1 + 64 * 72);       // 256
    int* sTgt = sSrc + 256;                  // 256
    float* sB1 = (float*)(sTgt + 256);       // 64

    const int tid = threadIdx.x;
    const int warp = tid >> 5, lane = tid & 31, g = lane >> 2, tig = lane & 3;

    // ---- stage weights ONCE (col pair-interleave; W1 also row-permuted) ----
#pragma unroll
    for (int i = 0; i < 8; i++) {
        int idx = i * 256 + tid;             // 2048 float4 over both tables
        int table = idx >> 10;
        int rem = idx & 1023;
        int r = rem >> 4, c4 = (rem & 15) * 4;
        const float* W = table ? W1 : We;
        uint32_t* dst = table ? sW1 : sWe;
        // W1: physical row rp = pos^{-1}(r): rp3<-r1, rp2<-r3, rp1<-r2; bits 5,4,0 fixed
        int rp = table
               ? ((r & 0x31) | ((r & 0x2) << 2) | ((r & 0x8) >> 1) | ((r & 0x4) >> 1))
               : r;
        float4 v = *(const float4*)(W + r * 64 + c4);
        float vv[4] = {v.x, v.y, v.z, v.w};
#pragma unroll
        for (int m = 0; m < 4; m++) {
            int c = c4 + m;
            int kpos = ((c >> 3) << 3) + (((c & 3) << 1) | ((c >> 2) & 1));
            dst[rp * 72 + kpos] = f2tf(vv[m]);
        }
    }
    if (tid < 64) sB1[tid] = b1[tid];
    __syncthreads();   // weights/bias visible; after this, warps are independent

    const int rb = warp * 32 + g;            // row slots: rb, rb+8, rb+16, rb+24
    uint32_t* A0 = sEA + rb * 68;
    uint32_t* A1 = A0 + 8 * 68;
    uint32_t* A2 = A0 + 16 * 68;
    uint32_t* A3 = A0 + 24 * 68;

    const uint32_t eaRowAddr = smem_u32(sEA) + (uint32_t)(warp * 32) * 68 * 4;
    const int wg0 = blockIdx.x * 8 + warp;   // global warp id

    // ---- prologue: prefetch EA + indices for first tile ----
    int rs = 0, rt = 0;
    if (wg0 < NTG) {
        const float* gsrc = ea + (size_t)wg0 * 32 * 64;
#pragma unroll
        for (int i = 0; i < 16; i++) {
            int idx = i * 32 + lane;
            int r = idx >> 4, c4 = (idx & 15) << 2;
            uint32_t dst = eaRowAddr + (uint32_t)(r * 68 + c4) * 4;
            asm volatile("cp.async.cg.shared.global [%0], [%1], 16;"
                         :: "r"(dst), "l"(gsrc + r * 64 + c4) : "memory");
        }
        rs = eidx[(size_t)wg0 * 32 + lane];
        rt = eidx[NE + (size_t)wg0 * 32 + lane];
    }
    asm volatile("cp.async.commit_group;" ::: "memory");

    for (int tile = wg0; tile < NTG; tile += WS) {
        const long long e0 = (long long)tile * 32;

        // indices for this warp's 32 edges (prefetched; clamp defensively)
        sSrc[warp * 32 + lane] = min(max(rs, 0), NN - 1);
        sTgt[warp * 32 + lane] = min(max(rt, 0), NN - 1);
        // prefetch next tile's indices (latency hidden by whole tile body)
        if (tile + WS < NTG) {
            rs = eidx[(size_t)(tile + WS) * 32 + lane];
            rt = eidx[NE + (size_t)(tile + WS) * 32 + lane];
        }
        asm volatile("cp.async.wait_group 0;" ::: "memory");
        __syncwarp();   // EA copies + index STS visible across the warp

        // ---- stage 1: H = EA @ We^T  (A raw f32 -> tf32 at consumption) ----
        float C[2][8][4];
#pragma unroll
        for (int s = 0; s < 2; s++)
#pragma unroll
            for (int nt = 0; nt < 8; nt++) { C[s][nt][0] = C[s][nt][1] = C[s][nt][2] = C[s][nt][3] = 0.f; }

#pragma unroll
        for (int kt = 0; kt < 8; kt++) {
            const int ko = kt * 8;
            uint32_t a00 = f2tf(__uint_as_float(A0[ko + tig]));
            uint32_t a01 = f2tf(__uint_as_float(A1[ko + tig]));
            uint32_t a02 = f2tf(__uint_as_float(A0[ko + tig + 4]));
            uint32_t a03 = f2tf(__uint_as_float(A1[ko + tig + 4]));
            uint32_t a10 = f2tf(__uint_as_float(A2[ko + tig]));
            uint32_t a11 = f2tf(__uint_as_float(A3[ko + tig]));
            uint32_t a12 = f2tf(__uint_as_float(A2[ko + tig + 4]));
            uint32_t a13 = f2tf(__uint_as_float(A3[ko + tig + 4]));
#pragma unroll
            for (int nt = 0; nt < 8; nt++) {
                uint2 b = *(const uint2*)(sWe + (nt * 8 + g) * 72 + ko + 2 * tig);
                mma8(C[0][nt], a00, a01, a02, a03, b.x, b.y);
                mma8(C[1][nt], a10, a11, a12, a13, b.x, b.y);
            }
        }

        // ---- gather (L1-cached, permuted tables) + GELU -> H to smem ----
#pragma unroll
        for (int s = 0; s < 4; s++) {
            const int row = rb + 8 * s;
            const int h = s >> 1, pb = (s & 1) * 2;
            const float* xs = g_xs + (size_t)sSrc[row] * 64 + tig * 4;
            const float* xt = g_xt + (size_t)sTgt[row] * 64 + tig * 4;
#pragma unroll
            for (int i = 0; i < 4; i++) {
                float4 p = *(const float4*)(xs + i * 16);
                float4 q = *(const float4*)(xt + i * 16);
                float v0 = C[h][2 * i + 0][pb + 0] + p.x + q.x;
                float v1 = C[h][2 * i + 0][pb + 1] + p.y + q.y;
                float v2 = C[h][2 * i + 1][pb + 0] + p.z + q.z;
                float v3 = C[h][2 * i + 1][pb + 1] + p.w + q.w;
                uint2 h0, h1;
                h0.x = f2tf(gelu_tanh(v0)); h0.y = f2tf(gelu_tanh(v1));
                h1.x = f2tf(gelu_tanh(v2)); h1.y = f2tf(gelu_tanh(v3));
                *(uint2*)(sEA + row * 68 + 16 * i + 2 * tig) = h0;       // col 8*(2i)
                *(uint2*)(sEA + row * 68 + 16 * i + 8 + 2 * tig) = h1;   // col 8*(2i+1)
            }
        }
        __syncwarp();  // H rows are warp-private

        // ---- stage 2: OUT = H @ W1p^T (N permuted) ----
#pragma unroll
        for (int s = 0; s < 2; s++)
#pragma unroll
            for (int nt = 0; nt < 8; nt++) { C[s][nt][0] = C[s][nt][1] = C[s][nt][2] = C[s][nt][3] = 0.f; }

#pragma unroll
        for (int kt = 0; kt < 8; kt++) {
            const int ko = kt * 8;
            uint32_t a00 = A0[ko + tig], a01 = A1[ko + tig];
            uint32_t a02 = A0[ko + tig + 4], a03 = A1[ko + tig + 4];
            uint32_t a10 = A2[ko + tig], a11 = A3[ko + tig];
            uint32_t a12 = A2[ko + tig + 4], a13 = A3[ko + tig + 4];
#pragma unroll
            for (int nt = 0; nt < 8; nt++) {
                uint2 b = *(const uint2*)(sW1 + (nt * 8 + g) * 72 + ko + 2 * tig);
                mma8(C[0][nt], a00, a01, a02, a03, b.x, b.y);
                mma8(C[1][nt], a10, a11, a12, a13, b.x, b.y);
            }
        }

        // ---- prefetch next tile's EA (rows free after stage-2 A loads) ----
        if (tile + WS < NTG) {
            const float* gsrc = ea + (size_t)(tile + WS) * 32 * 64;
#pragma unroll
            for (int i = 0; i < 16; i++) {
                int idx = i * 32 + lane;
                int r = idx >> 4, c4 = (idx & 15) << 2;
                uint32_t dst = eaRowAddr + (uint32_t)(r * 68 + c4) * 4;
                asm volatile("cp.async.cg.shared.global [%0], [%1], 16;"
                             :: "r"(dst), "l"(gsrc + r * 64 + c4) : "memory");
            }
        }
        asm volatile("cp.async.commit_group;" ::: "memory");

        // ---- epilogue: +b1, STG.128 at logical cols i*16 + tig*4 ----
        float4 bia[4];
#pragma unroll
        for (int i = 0; i < 4; i++) bia[i] = *(const float4*)(sB1 + i * 16 + tig * 4);
#pragma unroll
        for (int s = 0; s < 4; s++) {
            const int h = s >> 1, pb = (s & 1) * 2;
            float* orow = out + (size_t)(e0 + g + 8 * s) * 64 + tig * 4;
#pragma unroll
            for (int i = 0; i < 4; i++) {
                float4 v;
                v.x = C[h][2 * i + 0][pb + 0] + bia[i].x;
                v.y = C[h][2 * i + 0][pb + 1] + bia[i].y;
                v.z = C[h][2 * i + 1][pb + 0] + bia[i].z;
                v.w = C[h][2 * i + 1][pb + 1] + bia[i].w;
                *(float4*)(orow + i * 16) = v;
            }
        }
    }
}

extern "C" void kernel_launch(void* const* d_in, const int* in_sizes, int n_in,
                              void* d_out, int out_size) {
    const float* x   = (const float*)d_in[0];
    const int*   ei  = (const int*)d_in[1];     // int32 (JAX default x64-disabled)
    const float* ea  = (const float*)d_in[2];
    const float* We  = (const float*)d_in[3];
    const float* be  = (const float*)d_in[4];
    const float* Ws  = (const float*)d_in[5];
    const float* bs  = (const float*)d_in[6];
    const float* Wt  = (const float*)d_in[7];
    const float* bt  = (const float*)d_in[8];
    const float* W1  = (const float*)d_in[9];
    const float* b1  = (const float*)d_in[10];
    float* out = (float*)d_out;

    const size_t smem1 = (size_t)(64 * 132 + 128 * 132) * 4;                   // ~99 KB
    const size_t smem2 = (size_t)(256 * 68 + 2 * 64 * 72 + 512 + 64 + 16) * 4; // ~109 KB
    cudaFuncSetAttribute(node_proj_kernel, cudaFuncAttributeMaxDynamicSharedMemorySize, (int)smem1);
    cudaFuncSetAttribute(edge_mlp_kernel,  cudaFuncAttributeMaxDynamicSharedMemorySize, (int)smem2);

    node_proj_kernel<<<(NN + 63) / 64, 256, smem1>>>(x, Ws, bs, Wt, bt, be);
    edge_mlp_kernel<<<PGRID, 256, smem2>>>(ea, ei, We, W1, b1, out);
}

// round 11
// speedup vs baseline: 1.4490x; 1.1920x over previous
#include <cuda_runtime.h>
#include <cuda_fp16.h>
#include <cstdint>
#include <cstddef>

#define NE 1000000
#define NN 50000
#define NTG 31250                      // 32-edge groups (NE divisible by 32)
#define PGRID 296
#define WS (PGRID * 8)                 // total warps = tile stride

// node projections stored COLUMN-PERMUTED: logical feature c lives at
// pos(c) = (nt>>1)*16 + tig*4 + (nt&1)*2 + b   where c = 8*nt + 2*tig + b.
__device__ float g_xs[(size_t)NN * 64];
__device__ float g_xt[(size_t)NN * 64];

__device__ __forceinline__ uint32_t f2tf(float f) {
    uint32_t r;
    asm("cvt.rna.tf32.f32 %0, %1;" : "=r"(r) : "f"(f));
    return r;
}

__device__ __forceinline__ uint32_t smem_u32(const void* p) {
    uint32_t a;
    asm("{ .reg .u64 t; cvta.to.shared.u64 t, %1; cvt.u32.u64 %0, t; }" : "=r"(a) : "l"(p));
    return a;
}

__device__ __forceinline__ uint32_t pack_h2(float x, float y) {
    __half2 h = __float22half2_rn(make_float2(x, y));   // lo=x, hi=y
    return *reinterpret_cast<uint32_t*>(&h);
}

// tf32 m16n8k8 (kernel 1 only)
__device__ __forceinline__ void mma8(float c[4],
                                     uint32_t a0, uint32_t a1, uint32_t a2, uint32_t a3,
                                     uint32_t b0, uint32_t b1) {
    asm volatile(
        "mma.sync.aligned.m16n8k8.row.col.f32.tf32.tf32.f32 "
        "{%0,%1,%2,%3}, {%4,%5,%6,%7}, {%8,%9}, {%10,%11,%12,%13};\n"
        : "=f"(c[0]), "=f"(c[1]), "=f"(c[2]), "=f"(c[3])
        : "r"(a0), "r"(a1), "r"(a2), "r"(a3), "r"(b0), "r"(b1),
          "f"(c[0]), "f"(c[1]), "f"(c[2]), "f"(c[3]));
}

// fp16 m16n8k16 with fp32 accumulate (kernel 2)
__device__ __forceinline__ void mma16(float c[4],
                                      uint32_t a0, uint32_t a1, uint32_t a2, uint32_t a3,
                                      uint32_t b0, uint32_t b1) {
    asm volatile(
        "mma.sync.aligned.m16n8k16.row.col.f32.f16.f16.f32 "
        "{%0,%1,%2,%3}, {%4,%5,%6,%7}, {%8,%9}, {%10,%11,%12,%13};\n"
        : "=f"(c[0]), "=f"(c[1]), "=f"(c[2]), "=f"(c[3])
        : "r"(a0), "r"(a1), "r"(a2), "r"(a3), "r"(b0), "r"(b1),
          "f"(c[0]), "f"(c[1]), "f"(c[2]), "f"(c[3]));
}

// jax.nn.gelu approximate: gelu(v) = v * sigmoid(2u), u = sqrt(2/pi)(v+0.044715v^3)
__device__ __forceinline__ float gelu_tanh(float v) {
    float v3 = v * v * v;
    float m2u = -1.5957691216057308f * v - 0.07135481627260025f * v3;  // -2u
    float e = __expf(m2u);
    return __fdividef(v, 1.0f + e);
}

// ---------------------------------------------------------------------------
// Kernel 1: node projections, single pass (unchanged from R10).
// ---------------------------------------------------------------------------
__global__ __launch_bounds__(256)
void node_proj_kernel(const float* __restrict__ x,
                      const float* __restrict__ Ws, const float* __restrict__ bs,
                      const float* __restrict__ Wt, const float* __restrict__ bt,
                      const float* __restrict__ be) {
    extern __shared__ uint32_t sm1[];
    uint32_t* sX = sm1;                  // 64 x 132
    uint32_t* sW = sm1 + 64 * 132;       // 128 x 132 ([Ws;Wt])

    const int tid = threadIdx.x;
    const int warp = tid >> 5, lane = tid & 31, g = lane >> 2, tig = lane & 3;
    const int m0 = blockIdx.x * 64;

#pragma unroll
    for (int i = 0; i < 8; i++) {
        int idx = i * 256 + tid;
        int r = idx >> 5, c4 = (idx & 31) * 4;
        float4 v = make_float4(0.f, 0.f, 0.f, 0.f);
        if (m0 + r < NN) v = *(const float4*)(x + (size_t)(m0 + r) * 128 + c4);
        uint32_t* d = sX + r * 132 + c4;
        d[0] = f2tf(v.x); d[1] = f2tf(v.y); d[2] = f2tf(v.z); d[3] = f2tf(v.w);
    }
#pragma unroll
    for (int i = 0; i < 16; i++) {
        int idx = i * 256 + tid;
        int table = idx >> 11;
        int rem = idx & 2047;
        int r = rem >> 5, c4 = (rem & 31) * 4;
        const float* W = table ? Wt : Ws;
        float4 v = *(const float4*)(W + r * 128 + c4);
        uint32_t* d = sW + (table * 64 + r) * 132 + c4;
        d[0] = f2tf(v.x); d[1] = f2tf(v.y); d[2] = f2tf(v.z); d[3] = f2tf(v.w);
    }
    __syncthreads();

    const int mt = warp & 3, nh = warp >> 2;
    const int lr0 = mt * 16 + g;
    const uint32_t* A0 = sX + lr0 * 132;
    const uint32_t* A1 = A0 + 8 * 132;
    const uint32_t* Bbase = sW + nh * 64 * 132;
    const int gr0 = m0 + lr0;

    float C[8][4];
#pragma unroll
    for (int nt = 0; nt < 8; nt++) { C[nt][0] = C[nt][1] = C[nt][2] = C[nt][3] = 0.f; }

#pragma unroll
    for (int kt = 0; kt < 16; kt++) {
        uint32_t a0 = A0[kt * 8 + tig], a1 = A1[kt * 8 + tig];
        uint32_t a2 = A0[kt * 8 + tig + 4], a3 = A1[kt * 8 + tig + 4];
#pragma unroll
        for (int nt = 0; nt < 8; nt++) {
            const uint32_t* br = Bbase + (nt * 8 + g) * 132 + kt * 8;
            mma8(C[nt], a0, a1, a2, a3, br[tig], br[tig + 4]);
        }
    }

    float* dst = nh ? g_xt : g_xs;
#pragma unroll
    for (int nt = 0; nt < 8; nt++) {
        int c = nt * 8 + 2 * tig;
        int pos = (nt >> 1) * 16 + tig * 4 + (nt & 1) * 2;
        float bias0, bias1;
        if (nh == 0) { bias0 = bs[c] + be[c]; bias1 = bs[c + 1] + be[c + 1]; }
        else         { bias0 = bt[c];         bias1 = bt[c + 1]; }
        if (gr0 < NN) {
            float2 v = make_float2(C[nt][0] + bias0, C[nt][1] + bias1);
            *(float2*)(dst + (size_t)gr0 * 64 + pos) = v;
        }
        if (gr0 + 8 < NN) {
            float2 v = make_float2(C[nt][2] + bias0, C[nt][3] + bias1);
            *(float2*)(dst + (size_t)(gr0 + 8) * 64 + pos) = v;
        }
    }
}

// ---------------------------------------------------------------------------
// Kernel 2: fused edge MLP — fp16 m16n8k16 tensor path.
// Barrier-free per-warp pipeline; 32 edges per warp-tile.
// sEA: 256 rows x 72 words (raw f32 EA; H overwrites words 0..31 as f16x2
//   with pair-interleave: chunk kt at words 8kt..8kt+7, pair p' at word
//   2*(p'&3)+(p'>>2) so thread (g,tig) reads a0/a2 via one LDS.64).
// Weights f16x2, 64 rows x 40 words, same word mapping (b0/b1 via LDS.64);
// W1 rows permuted rp = pos^{-1}(r). Bank math: 8g+2tig distinct per
// half-warp for all LDS/STS.64 patterns.
// ---------------------------------------------------------------------------
#define EAS 72
#define WSTR 40

__global__ __launch_bounds__(256, 2)
void edge_mlp_kernel(const float* __restrict__ ea,
                     const int* __restrict__ eidx,
                     const float* __restrict__ We,
                     const float* __restrict__ W1,
                     const float* __restrict__ b1,
                     float* __restrict__ out) {
    extern __shared__ uint32_t sm2[];
    uint32_t* sEA = sm2;                       // 256 x 72
    uint32_t* sWe = sm2 + 256 * EAS;           // 64 x 40 (f16x2 words)
    uint32_t* sW1 = sWe + 64 * WSTR;           // 64 x 40
    int* sSrc = (int*)(sW1 + 64 * WSTR);       // 256
    int* sTgt = sSrc + 256;                    // 256
    float* sB1 = (float*)(sTgt + 256);         // 64

    const int tid = threadIdx.x;
    const int warp = tid >> 5, lane = tid & 31, g = lane >> 2, tig = lane & 3;

    // ---- stage weights ONCE as f16x2 (word map; W1 rows permuted) ----
#pragma unroll
    for (int i = 0; i < 8; i++) {
        int idx = i * 256 + tid;               // 2048 float4 over both tables
        int table = idx >> 10;
        int rem = idx & 1023;
        int r = rem >> 4, c4 = (rem & 15) * 4;
        const float* W = table ? W1 : We;
        uint32_t* dst = table ? sW1 : sWe;
        int rp = table
               ? ((r & 0x31) | ((r & 0x2) << 2) | ((r & 0x8) >> 1) | ((r & 0x4) >> 1))
               : r;
        float4 v = *(const float4*)(W + r * 64 + c4);
        // pairs (c4,c4+1) and (c4+2,c4+3): word = 8*(c>>4) + 2*(p'&3) + (p'>>2), p'=(c>>1)&7
        int p1 = (c4 >> 1) & 7;
        int w1 = ((c4 >> 4) << 3) + 2 * (p1 & 3) + (p1 >> 2);
        int p2 = ((c4 + 2) >> 1) & 7;
        int w2 = (((c4 + 2) >> 4) << 3) + 2 * (p2 & 3) + (p2 >> 2);
        dst[rp * WSTR + w1] = pack_h2(v.x, v.y);
        dst[rp * WSTR + w2] = pack_h2(v.z, v.w);
    }
    if (tid < 64) sB1[tid] = b1[tid];
    __syncthreads();   // weights/bias visible; after this, warps are independent

    const int rb = warp * 32 + g;              // row slots: rb, rb+8, rb+16, rb+24
    uint32_t* A0 = sEA + rb * EAS;
    uint32_t* A1 = A0 + 8 * EAS;
    uint32_t* A2 = A0 + 16 * EAS;
    uint32_t* A3 = A0 + 24 * EAS;

    const uint32_t eaRowAddr = smem_u32(sEA) + (uint32_t)(warp * 32) * EAS * 4;
    const int wg0 = blockIdx.x * 8 + warp;     // global warp id

    // ---- prologue: prefetch EA + indices for first tile ----
    int rs = 0, rt = 0;
    if (wg0 < NTG) {
        const float* gsrc = ea + (size_t)wg0 * 32 * 64;
#pragma unroll
        for (int i = 0; i < 16; i++) {
            int idx = i * 32 + lane;
            int r = idx >> 4, c4 = (idx & 15) << 2;
            uint32_t dst = eaRowAddr + (uint32_t)(r * EAS + c4) * 4;
            asm volatile("cp.async.cg.shared.global [%0], [%1], 16;"
                         :: "r"(dst), "l"(gsrc + r * 64 + c4) : "memory");
        }
        rs = eidx[(size_t)wg0 * 32 + lane];
        rt = eidx[NE + (size_t)wg0 * 32 + lane];
    }
    asm volatile("cp.async.commit_group;" ::: "memory");

    for (int tile = wg0; tile < NTG; tile += WS) {
        const long long e0 = (long long)tile * 32;

        sSrc[warp * 32 + lane] = min(max(rs, 0), NN - 1);
        sTgt[warp * 32 + lane] = min(max(rt, 0), NN - 1);
        if (tile + WS < NTG) {
            rs = eidx[(size_t)(tile + WS) * 32 + lane];
            rt = eidx[NE + (size_t)(tile + WS) * 32 + lane];
        }
        asm volatile("cp.async.wait_group 0;" ::: "memory");
        __syncwarp();

        // ---- stage 1: H = EA @ We^T  (f32 pairs -> f16x2 at consumption) ----
        float C[2][8][4];
#pragma unroll
        for (int s = 0; s < 2; s++)
#pragma unroll
            for (int nt = 0; nt < 8; nt++) { C[s][nt][0] = C[s][nt][1] = C[s][nt][2] = C[s][nt][3] = 0.f; }

#pragma unroll
        for (int kt = 0; kt < 4; kt++) {
            const int base = 16 * kt + 2 * tig;
            float2 l0 = *(const float2*)(A0 + base), h0 = *(const float2*)(A0 + base + 8);
            float2 l1 = *(const float2*)(A1 + base), h1 = *(const float2*)(A1 + base + 8);
            float2 l2 = *(const float2*)(A2 + base), h2 = *(const float2*)(A2 + base + 8);
            float2 l3 = *(const float2*)(A3 + base), h3 = *(const float2*)(A3 + base + 8);
            uint32_t a00 = pack_h2(l0.x, l0.y), a02 = pack_h2(h0.x, h0.y);
            uint32_t a01 = pack_h2(l1.x, l1.y), a03 = pack_h2(h1.x, h1.y);
            uint32_t a10 = pack_h2(l2.x, l2.y), a12 = pack_h2(h2.x, h2.y);
            uint32_t a11 = pack_h2(l3.x, l3.y), a13 = pack_h2(h3.x, h3.y);
#pragma unroll
            for (int nt = 0; nt < 8; nt++) {
                uint2 b = *(const uint2*)(sWe + (nt * 8 + g) * WSTR + 8 * kt + 2 * tig);
                mma16(C[0][nt], a00, a01, a02, a03, b.x, b.y);
                mma16(C[1][nt], a10, a11, a12, a13, b.x, b.y);
            }
        }

        // ---- gather (L1-cached, permuted tables) + GELU -> H (f16x2) ----
#pragma unroll
        for (int s = 0; s < 4; s++) {
            const int row = rb + 8 * s;
            const int h = s >> 1, pb = (s & 1) * 2;
            const float* xs = g_xs + (size_t)sSrc[row] * 64 + tig * 4;
            const float* xt = g_xt + (size_t)sTgt[row] * 64 + tig * 4;
#pragma unroll
            for (int i = 0; i < 4; i++) {
                float4 p = *(const float4*)(xs + i * 16);
                float4 q = *(const float4*)(xt + i * 16);
                float v0 = C[h][2 * i + 0][pb + 0] + p.x + q.x;
                float v1 = C[h][2 * i + 0][pb + 1] + p.y + q.y;
                float v2 = C[h][2 * i + 1][pb + 0] + p.z + q.z;
                float v3 = C[h][2 * i + 1][pb + 1] + p.w + q.w;
                uint2 w;
                w.x = pack_h2(gelu_tanh(v0), gelu_tanh(v1));   // nt=2i  -> word 8i+2tig
                w.y = pack_h2(gelu_tanh(v2), gelu_tanh(v3));   // nt=2i+1-> word 8i+2tig+1
                *(uint2*)(sEA + row * EAS + 8 * i + 2 * tig) = w;
            }
        }
        __syncwarp();  // H rows are warp-private

        // ---- stage 2: OUT = H @ W1p^T (N permuted) ----
#pragma unroll
        for (int s = 0; s < 2; s++)
#pragma unroll
            for (int nt = 0; nt < 8; nt++) { C[s][nt][0] = C[s][nt][1] = C[s][nt][2] = C[s][nt][3] = 0.f; }

#pragma unroll
        for (int kt = 0; kt < 4; kt++) {
            const int base = 8 * kt + 2 * tig;
            uint2 q0 = *(const uint2*)(A0 + base);   // (a0 = k-lo, a2 = k-hi) row g
            uint2 q1 = *(const uint2*)(A1 + base);   // row g+8
            uint2 q2 = *(const uint2*)(A2 + base);   // row g+16
            uint2 q3 = *(const uint2*)(A3 + base);   // row g+24
#pragma unroll
            for (int nt = 0; nt < 8; nt++) {
                uint2 b = *(const uint2*)(sW1 + (nt * 8 + g) * WSTR + base);
                mma16(C[0][nt], q0.x, q1.x, q0.y, q1.y, b.x, b.y);
                mma16(C[1][nt], q2.x, q3.x, q2.y, q3.y, b.x, b.y);
            }
        }

        // ---- prefetch next tile's EA ----
        if (tile + WS < NTG) {
            const float* gsrc = ea + (size_t)(tile + WS) * 32 * 64;
#pragma unroll
            for (int i = 0; i < 16; i++) {
                int idx = i * 32 + lane;
                int r = idx >> 4, c4 = (idx & 15) << 2;
                uint32_t dst = eaRowAddr + (uint32_t)(r * EAS + c4) * 4;
                asm volatile("cp.async.cg.shared.global [%0], [%1], 16;"
                             :: "r"(dst), "l"(gsrc + r * 64 + c4) : "memory");
            }
        }
        asm volatile("cp.async.commit_group;" ::: "memory");

        // ---- epilogue: +b1, STG.128 at logical cols i*16 + tig*4 ----
        float4 bia[4];
#pragma unroll
        for (int i = 0; i < 4; i++) bia[i] = *(const float4*)(sB1 + i * 16 + tig * 4);
#pragma unroll
        for (int s = 0; s < 4; s++) {
            const int h = s >> 1, pb = (s & 1) * 2;
            float* orow = out + (size_t)(e0 + g + 8 * s) * 64 + tig * 4;
#pragma unroll
            for (int i = 0; i < 4; i++) {
                float4 v;
                v.x = C[h][2 * i + 0][pb + 0] + bia[i].x;
                v.y = C[h][2 * i + 0][pb + 1] + bia[i].y;
                v.z = C[h][2 * i + 1][pb + 0] + bia[i].z;
                v.w = C[h][2 * i + 1][pb + 1] + bia[i].w;
                *(float4*)(orow + i * 16) = v;
            }
        }
    }
}

extern "C" void kernel_launch(void* const* d_in, const int* in_sizes, int n_in,
                              void* d_out, int out_size) {
    const float* x   = (const float*)d_in[0];
    const int*   ei  = (const int*)d_in[1];     // int32 (JAX default x64-disabled)
    const float* ea  = (const float*)d_in[2];
    const float* We  = (const float*)d_in[3];
    const float* be  = (const float*)d_in[4];
    const float* Ws  = (const float*)d_in[5];
    const float* bs  = (const float*)d_in[6];
    const float* Wt  = (const float*)d_in[7];
    const float* bt  = (const float*)d_in[8];
    const float* W1  = (const float*)d_in[9];
    const float* b1  = (const float*)d_in[10];
    float* out = (float*)d_out;

    const size_t smem1 = (size_t)(64 * 132 + 128 * 132) * 4;                       // ~99 KB
    const size_t smem2 = (size_t)(256 * EAS + 2 * 64 * WSTR + 512 + 64 + 16) * 4;  // ~94 KB
    cudaFuncSetAttribute(node_proj_kernel, cudaFuncAttributeMaxDynamicSharedMemorySize, (int)smem1);
    cudaFuncSetAttribute(edge_mlp_kernel,  cudaFuncAttributeMaxDynamicSharedMemorySize, (int)smem2);

    node_proj_kernel<<<(NN + 63) / 64, 256, smem1>>>(x, Ws, bs, Wt, bt, be);
    edge_mlp_kernel<<<PGRID, 256, smem2>>>(ea, ei, We, W1, b1, out);
}

// round 12
// speedup vs baseline: 1.5275x; 1.0542x over previous
#include <cuda_runtime.h>
#include <cuda_fp16.h>
#include <cstdint>
#include <cstddef>

#define NE 1000000
#define NN 50000
#define NTG 31250                      // 32-edge groups (NE divisible by 32)
#define PGRID 296
#define WS (PGRID * 8)                 // total warps = tile stride

// node projections stored as f16, COLUMN-PERMUTED with pos3:
// logical feature c = 8nt + 2tig + b lives at half-index pos3(c) = 16*tig + 2*nt + b.
// => each mma-fragment owner thread's 16 features are 32 contiguous bytes.
__device__ __half g_xs[(size_t)NN * 64];
__device__ __half g_xt[(size_t)NN * 64];

__device__ __forceinline__ uint32_t f2tf(float f) {
    uint32_t r;
    asm("cvt.rna.tf32.f32 %0, %1;" : "=r"(r) : "f"(f));
    return r;
}

__device__ __forceinline__ uint32_t smem_u32(const void* p) {
    uint32_t a;
    asm("{ .reg .u64 t; cvta.to.shared.u64 t, %1; cvt.u32.u64 %0, t; }" : "=r"(a) : "l"(p));
    return a;
}

__device__ __forceinline__ uint32_t pack_h2(float x, float y) {
    __half2 h = __float22half2_rn(make_float2(x, y));   // lo=x, hi=y
    return *reinterpret_cast<uint32_t*>(&h);
}

// tf32 m16n8k8 (kernel 1 only)
__device__ __forceinline__ void mma8(float c[4],
                                     uint32_t a0, uint32_t a1, uint32_t a2, uint32_t a3,
                                     uint32_t b0, uint32_t b1) {
    asm volatile(
        "mma.sync.aligned.m16n8k8.row.col.f32.tf32.tf32.f32 "
        "{%0,%1,%2,%3}, {%4,%5,%6,%7}, {%8,%9}, {%10,%11,%12,%13};\n"
        : "=f"(c[0]), "=f"(c[1]), "=f"(c[2]), "=f"(c[3])
        : "r"(a0), "r"(a1), "r"(a2), "r"(a3), "r"(b0), "r"(b1),
          "f"(c[0]), "f"(c[1]), "f"(c[2]), "f"(c[3]));
}

// fp16 m16n8k16 with fp32 accumulate (kernel 2)
__device__ __forceinline__ void mma16(float c[4],
                                      uint32_t a0, uint32_t a1, uint32_t a2, uint32_t a3,
                                      uint32_t b0, uint32_t b1) {
    asm volatile(
        "mma.sync.aligned.m16n8k16.row.col.f32.f16.f16.f32 "
        "{%0,%1,%2,%3}, {%4,%5,%6,%7}, {%8,%9}, {%10,%11,%12,%13};\n"
        : "=f"(c[0]), "=f"(c[1]), "=f"(c[2]), "=f"(c[3])
        : "r"(a0), "r"(a1), "r"(a2), "r"(a3), "r"(b0), "r"(b1),
          "f"(c[0]), "f"(c[1]), "f"(c[2]), "f"(c[3]));
}

// jax.nn.gelu approximate: gelu(v) = v * sigmoid(2u), u = sqrt(2/pi)(v+0.044715v^3)
__device__ __forceinline__ float gelu_tanh(float v) {
    float v3 = v * v * v;
    float m2u = -1.5957691216057308f * v - 0.07135481627260025f * v3;  // -2u
    float e = __expf(m2u);
    return __fdividef(v, 1.0f + e);
}

// ---------------------------------------------------------------------------
// Kernel 1: node projections, single pass; outputs f16 at pos3-permuted cols.
// ---------------------------------------------------------------------------
__global__ __launch_bounds__(256)
void node_proj_kernel(const float* __restrict__ x,
                      const float* __restrict__ Ws, const float* __restrict__ bs,
                      const float* __restrict__ Wt, const float* __restrict__ bt,
                      const float* __restrict__ be) {
    extern __shared__ uint32_t sm1[];
    uint32_t* sX = sm1;                  // 64 x 132
    uint32_t* sW = sm1 + 64 * 132;       // 128 x 132 ([Ws;Wt])

    const int tid = threadIdx.x;
    const int warp = tid >> 5, lane = tid & 31, g = lane >> 2, tig = lane & 3;
    const int m0 = blockIdx.x * 64;

#pragma unroll
    for (int i = 0; i < 8; i++) {
        int idx = i * 256 + tid;
        int r = idx >> 5, c4 = (idx & 31) * 4;
        float4 v = make_float4(0.f, 0.f, 0.f, 0.f);
        if (m0 + r < NN) v = *(const float4*)(x + (size_t)(m0 + r) * 128 + c4);
        uint32_t* d = sX + r * 132 + c4;
        d[0] = f2tf(v.x); d[1] = f2tf(v.y); d[2] = f2tf(v.z); d[3] = f2tf(v.w);
    }
#pragma unroll
    for (int i = 0; i < 16; i++) {
        int idx = i * 256 + tid;
        int table = idx >> 11;
        int rem = idx & 2047;
        int r = rem >> 5, c4 = (rem & 31) * 4;
        const float* W = table ? Wt : Ws;
        float4 v = *(const float4*)(W + r * 128 + c4);
        uint32_t* d = sW + (table * 64 + r) * 132 + c4;
        d[0] = f2tf(v.x); d[1] = f2tf(v.y); d[2] = f2tf(v.z); d[3] = f2tf(v.w);
    }
    __syncthreads();

    const int mt = warp & 3, nh = warp >> 2;
    const int lr0 = mt * 16 + g;
    const uint32_t* A0 = sX + lr0 * 132;
    const uint32_t* A1 = A0 + 8 * 132;
    const uint32_t* Bbase = sW + nh * 64 * 132;
    const int gr0 = m0 + lr0;

    float C[8][4];
#pragma unroll
    for (int nt = 0; nt < 8; nt++) { C[nt][0] = C[nt][1] = C[nt][2] = C[nt][3] = 0.f; }

#pragma unroll
    for (int kt = 0; kt < 16; kt++) {
        uint32_t a0 = A0[kt * 8 + tig], a1 = A1[kt * 8 + tig];
        uint32_t a2 = A0[kt * 8 + tig + 4], a3 = A1[kt * 8 + tig + 4];
#pragma unroll
        for (int nt = 0; nt < 8; nt++) {
            const uint32_t* br = Bbase + (nt * 8 + g) * 132 + kt * 8;
            mma8(C[nt], a0, a1, a2, a3, br[tig], br[tig + 4]);
        }
    }

    __half* dst = nh ? g_xt : g_xs;
#pragma unroll
    for (int nt = 0; nt < 8; nt++) {
        int c = nt * 8 + 2 * tig;                      // logical col (b=0)
        int hp = 16 * tig + 2 * nt;                    // pos3 half-offset (b=0)
        float bias0, bias1;
        if (nh == 0) { bias0 = bs[c] + be[c]; bias1 = bs[c + 1] + be[c + 1]; }
        else         { bias0 = bt[c];         bias1 = bt[c + 1]; }
        if (gr0 < NN) {
            *(uint32_t*)(dst + (size_t)gr0 * 64 + hp) =
                pack_h2(C[nt][0] + bias0, C[nt][1] + bias1);
        }
        if (gr0 + 8 < NN) {
            *(uint32_t*)(dst + (size_t)(gr0 + 8) * 64 + hp) =
                pack_h2(C[nt][2] + bias0, C[nt][3] + bias1);
        }
    }
}

// ---------------------------------------------------------------------------
// Kernel 2: fused edge MLP — fp16 m16n8k16 tensor path (R11 structure).
// Gathers: f16 tables, pos3 layout -> 2x LDG.128 per row per table, one 128B
// line per node row. W1/epilogue permutation unchanged from R11.
// ---------------------------------------------------------------------------
#define EAS 72
#define WSTR 40

__global__ __launch_bounds__(256, 2)
void edge_mlp_kernel(const float* __restrict__ ea,
                     const int* __restrict__ eidx,
                     const float* __restrict__ We,
                     const float* __restrict__ W1,
                     const float* __restrict__ b1,
                     float* __restrict__ out) {
    extern __shared__ uint32_t sm2[];
    uint32_t* sEA = sm2;                       // 256 x 72
    uint32_t* sWe = sm2 + 256 * EAS;           // 64 x 40 (f16x2 words)
    uint32_t* sW1 = sWe + 64 * WSTR;           // 64 x 40
    int* sSrc = (int*)(sW1 + 64 * WSTR);       // 256
    int* sTgt = sSrc + 256;                    // 256
    float* sB1 = (float*)(sTgt + 256);         // 64

    const int tid = threadIdx.x;
    const int warp = tid >> 5, lane = tid & 31, g = lane >> 2, tig = lane & 3;

    // ---- stage weights ONCE as f16x2 (word map; W1 rows permuted, old map) ----
#pragma unroll
    for (int i = 0; i < 8; i++) {
        int idx = i * 256 + tid;               // 2048 float4 over both tables
        int table = idx >> 10;
        int rem = idx & 1023;
        int r = rem >> 4, c4 = (rem & 15) * 4;
        const float* W = table ? W1 : We;
        uint32_t* dst = table ? sW1 : sWe;
        int rp = table
               ? ((r & 0x31) | ((r & 0x2) << 2) | ((r & 0x8) >> 1) | ((r & 0x4) >> 1))
               : r;
        float4 v = *(const float4*)(W + r * 64 + c4);
        int p1 = (c4 >> 1) & 7;
        int w1 = ((c4 >> 4) << 3) + 2 * (p1 & 3) + (p1 >> 2);
        int p2 = ((c4 + 2) >> 1) & 7;
        int w2 = (((c4 + 2) >> 4) << 3) + 2 * (p2 & 3) + (p2 >> 2);
        dst[rp * WSTR + w1] = pack_h2(v.x, v.y);
        dst[rp * WSTR + w2] = pack_h2(v.z, v.w);
    }
    if (tid < 64) sB1[tid] = b1[tid];
    __syncthreads();   // weights/bias visible; after this, warps are independent

    const int rb = warp * 32 + g;              // row slots: rb, rb+8, rb+16, rb+24
    uint32_t* A0 = sEA + rb * EAS;
    uint32_t* A1 = A0 + 8 * EAS;
    uint32_t* A2 = A0 + 16 * EAS;
    uint32_t* A3 = A0 + 24 * EAS;

    const uint32_t eaRowAddr = smem_u32(sEA) + (uint32_t)(warp * 32) * EAS * 4;
    const int wg0 = blockIdx.x * 8 + warp;     // global warp id

    // ---- prologue: prefetch EA + indices for first tile ----
    int rs = 0, rt = 0;
    if (wg0 < NTG) {
        const float* gsrc = ea + (size_t)wg0 * 32 * 64;
#pragma unroll
        for (int i = 0; i < 16; i++) {
            int idx = i * 32 + lane;
            int r = idx >> 4, c4 = (idx & 15) << 2;
            uint32_t dst = eaRowAddr + (uint32_t)(r * EAS + c4) * 4;
            asm volatile("cp.async.cg.shared.global [%0], [%1], 16;"
                         :: "r"(dst), "l"(gsrc + r * 64 + c4) : "memory");
        }
        rs = eidx[(size_t)wg0 * 32 + lane];
        rt = eidx[NE + (size_t)wg0 * 32 + lane];
    }
    asm volatile("cp.async.commit_group;" ::: "memory");

    for (int tile = wg0; tile < NTG; tile += WS) {
        const long long e0 = (long long)tile * 32;

        sSrc[warp * 32 + lane] = min(max(rs, 0), NN - 1);
        sTgt[warp * 32 + lane] = min(max(rt, 0), NN - 1);
        if (tile + WS < NTG) {
            rs = eidx[(size_t)(tile + WS) * 32 + lane];
            rt = eidx[NE + (size_t)(tile + WS) * 32 + lane];
        }
        asm volatile("cp.async.wait_group 0;" ::: "memory");
        __syncwarp();

        // ---- stage 1: H = EA @ We^T  (f32 pairs -> f16x2 at consumption) ----
        float C[2][8][4];
#pragma unroll
        for (int s = 0; s < 2; s++)
#pragma unroll
            for (int nt = 0; nt < 8; nt++) { C[s][nt][0] = C[s][nt][1] = C[s][nt][2] = C[s][nt][3] = 0.f; }

#pragma unroll
        for (int kt = 0; kt < 4; kt++) {
            const int base = 16 * kt + 2 * tig;
            float2 l0 = *(const float2*)(A0 + base), h0 = *(const float2*)(A0 + base + 8);
            float2 l1 = *(const float2*)(A1 + base), h1 = *(const float2*)(A1 + base + 8);
            float2 l2 = *(const float2*)(A2 + base), h2 = *(const float2*)(A2 + base + 8);
            float2 l3 = *(const float2*)(A3 + base), h3 = *(const float2*)(A3 + base + 8);
            uint32_t a00 = pack_h2(l0.x, l0.y), a02 = pack_h2(h0.x, h0.y);
            uint32_t a01 = pack_h2(l1.x, l1.y), a03 = pack_h2(h1.x, h1.y);
            uint32_t a10 = pack_h2(l2.x, l2.y), a12 = pack_h2(h2.x, h2.y);
            uint32_t a11 = pack_h2(l3.x, l3.y), a13 = pack_h2(h3.x, h3.y);
#pragma unroll
            for (int nt = 0; nt < 8; nt++) {
                uint2 b = *(const uint2*)(sWe + (nt * 8 + g) * WSTR + 8 * kt + 2 * tig);
                mma16(C[0][nt], a00, a01, a02, a03, b.x, b.y);
                mma16(C[1][nt], a10, a11, a12, a13, b.x, b.y);
            }
        }

        // ---- gather (f16 tables, pos3: 2x LDG.128 per row per table) + GELU ----
#pragma unroll
        for (int s = 0; s < 4; s++) {
            const int row = rb + 8 * s;
            const int h = s >> 1, pb = (s & 1) * 2;
            const __half* xs = g_xs + (size_t)sSrc[row] * 64 + tig * 16;
            const __half* xt = g_xt + (size_t)sTgt[row] * 64 + tig * 16;
            uint4 pa = *(const uint4*)xs;          // halves 0..7  -> nt 0..3
            uint4 pbv = *(const uint4*)(xs + 8);   // halves 8..15 -> nt 4..7
            uint4 qa = *(const uint4*)xt;
            uint4 qb = *(const uint4*)(xt + 8);
            const __half2* ph = (const __half2*)&pa;   // [4]
            const __half2* ph2 = (const __half2*)&pbv;
            const __half2* qh = (const __half2*)&qa;
            const __half2* qh2 = (const __half2*)&qb;
#pragma unroll
            for (int i = 0; i < 4; i++) {
                // nt = 2i and 2i+1
                float2 px0 = __half22float2(2 * i < 4 ? ph[2 * i] : ph2[2 * i - 4]);
                float2 px1 = __half22float2(2 * i + 1 < 4 ? ph[2 * i + 1] : ph2[2 * i - 3]);
                float2 qx0 = __half22float2(2 * i < 4 ? qh[2 * i] : qh2[2 * i - 4]);
                float2 qx1 = __half22float2(2 * i + 1 < 4 ? qh[2 * i + 1] : qh2[2 * i - 3]);
                float v0 = C[h][2 * i + 0][pb + 0] + px0.x + qx0.x;
                float v1 = C[h][2 * i + 0][pb + 1] + px0.y + qx0.y;
                float v2 = C[h][2 * i + 1][pb + 0] + px1.x + qx1.x;
                float v3 = C[h][2 * i + 1][pb + 1] + px1.y + qx1.y;
                uint2 w;
                w.x = pack_h2(gelu_tanh(v0), gelu_tanh(v1));   // nt=2i  -> word 8i+2tig
                w.y = pack_h2(gelu_tanh(v2), gelu_tanh(v3));   // nt=2i+1-> word 8i+2tig+1
                *(uint2*)(sEA + row * EAS + 8 * i + 2 * tig) = w;
            }
        }
        __syncwarp();  // H rows are warp-private

        // ---- stage 2: OUT = H @ W1p^T (N permuted) ----
#pragma unroll
        for (int s = 0; s < 2; s++)
#pragma unroll
            for (int nt = 0; nt < 8; nt++) { C[s][nt][0] = C[s][nt][1] = C[s][nt][2] = C[s][nt][3] = 0.f; }

#pragma unroll
        for (int kt = 0; kt < 4; kt++) {
            const int base = 8 * kt + 2 * tig;
            uint2 q0 = *(const uint2*)(A0 + base);
            uint2 q1 = *(const uint2*)(A1 + base);
            uint2 q2 = *(const uint2*)(A2 + base);
            uint2 q3 = *(const uint2*)(A3 + base);
#pragma unroll
            for (int nt = 0; nt < 8; nt++) {
                uint2 b = *(const uint2*)(sW1 + (nt * 8 + g) * WSTR + base);
                mma16(C[0][nt], q0.x, q1.x, q0.y, q1.y, b.x, b.y);
                mma16(C[1][nt], q2.x, q3.x, q2.y, q3.y, b.x, b.y);
            }
        }

        // ---- prefetch next tile's EA ----
        if (tile + WS < NTG) {
            const float* gsrc = ea + (size_t)(tile + WS) * 32 * 64;
#pragma unroll
            for (int i = 0; i < 16; i++) {
                int idx = i * 32 + lane;
                int r = idx >> 4, c4 = (idx & 15) << 2;
                uint32_t dst = eaRowAddr + (uint32_t)(r * EAS + c4) * 4;
                asm volatile("cp.async.cg.shared.global [%0], [%1], 16;"
                             :: "r"(dst), "l"(gsrc + r * 64 + c4) : "memory");
            }
        }
        asm volatile("cp.async.commit_group;" ::: "memory");

        // ---- epilogue: +b1, STG.128 at logical cols i*16 + tig*4 (old map) ----
        float4 bia[4];
#pragma unroll
        for (int i = 0; i < 4; i++) bia[i] = *(const float4*)(sB1 + i * 16 + tig * 4);
#pragma unroll
        for (int s = 0; s < 4; s++) {
            const int h = s >> 1, pb = (s & 1) * 2;
            float* orow = out + (size_t)(e0 + g + 8 * s) * 64 + tig * 4;
#pragma unroll
            for (int i = 0; i < 4; i++) {
                float4 v;
                v.x = C[h][2 * i + 0][pb + 0] + bia[i].x;
                v.y = C[h][2 * i + 0][pb + 1] + bia[i].y;
                v.z = C[h][2 * i + 1][pb + 0] + bia[i].z;
                v.w = C[h][2 * i + 1][pb + 1] + bia[i].w;
                *(float4*)(orow + i * 16) = v;
            }
        }
    }
}

extern "C" void kernel_launch(void* const* d_in, const int* in_sizes, int n_in,
                              void* d_out, int out_size) {
    const float* x   = (const float*)d_in[0];
    const int*   ei  = (const int*)d_in[1];     // int32 (JAX default x64-disabled)
    const float* ea  = (const float*)d_in[2];
    const float* We  = (const float*)d_in[3];
    const float* be  = (const float*)d_in[4];
    const float* Ws  = (const float*)d_in[5];
    const float* bs  = (const float*)d_in[6];
    const float* Wt  = (const float*)d_in[7];
    const float* bt  = (const float*)d_in[8];
    const float* W1  = (const float*)d_in[9];
    const float* b1  = (const float*)d_in[10];
    float* out = (float*)d_out;

    const size_t smem1 = (size_t)(64 * 132 + 128 * 132) * 4;                       // ~99 KB
    const size_t smem2 = (size_t)(256 * EAS + 2 * 64 * WSTR + 512 + 64 + 16) * 4;  // ~94 KB
    cudaFuncSetAttribute(node_proj_kernel, cudaFuncAttributeMaxDynamicSharedMemorySize, (int)smem1);
    cudaFuncSetAttribute(edge_mlp_kernel,  cudaFuncAttributeMaxDynamicSharedMemorySize, (int)smem2);

    node_proj_kernel<<<(NN + 63) / 64, 256, smem1>>>(x, Ws, bs, Wt, bt, be);
    edge_mlp_kernel<<<PGRID, 256, smem2>>>(ea, ei, We, W1, b1, out);
}

// round 13
// speedup vs baseline: 1.6638x; 1.0892x over previous
#include <cuda_runtime.h>
#include <cuda_fp16.h>
#include <cstdint>
#include <cstddef>

#define NE 1000000
#define NN 50000
#define NTG 31250                      // 32-edge groups (NE divisible by 32)
#define PGRID 296
#define WS (PGRID * 8)                 // total warps = tile stride

// node projections stored as f16, COLUMN-PERMUTED with pos3:
// logical feature c = 8nt + 2tig + b lives at half-index pos3(c) = 16*tig + 2*nt + b.
__device__ __half g_xs[(size_t)NN * 64];
__device__ __half g_xt[(size_t)NN * 64];

__device__ __forceinline__ uint32_t smem_u32(const void* p) {
    uint32_t a;
    asm("{ .reg .u64 t; cvta.to.shared.u64 t, %1; cvt.u32.u64 %0, t; }" : "=r"(a) : "l"(p));
    return a;
}

__device__ __forceinline__ uint32_t pack_h2(float x, float y) {
    __half2 h = __float22half2_rn(make_float2(x, y));   // lo=x, hi=y
    return *reinterpret_cast<uint32_t*>(&h);
}

// fp16 m16n8k16 with fp32 accumulate
__device__ __forceinline__ void mma16(float c[4],
                                      uint32_t a0, uint32_t a1, uint32_t a2, uint32_t a3,
                                      uint32_t b0, uint32_t b1) {
    asm volatile(
        "mma.sync.aligned.m16n8k16.row.col.f32.f16.f16.f32 "
        "{%0,%1,%2,%3}, {%4,%5,%6,%7}, {%8,%9}, {%10,%11,%12,%13};\n"
        : "=f"(c[0]), "=f"(c[1]), "=f"(c[2]), "=f"(c[3])
        : "r"(a0), "r"(a1), "r"(a2), "r"(a3), "r"(b0), "r"(b1),
          "f"(c[0]), "f"(c[1]), "f"(c[2]), "f"(c[3]));
}

// jax.nn.gelu approximate via MUFU.TANH: 0.5v(1+tanh(0.79788456(v+0.044715v^3)))
__device__ __forceinline__ float gelu_tanh(float v) {
    float u = v * fmaf(0.035677408136300125f, v * v, 0.7978845608028654f);
    float t;
    asm("tanh.approx.f32 %0, %1;" : "=f"(t) : "f"(u));
    float hv = 0.5f * v;
    return fmaf(hv, t, hv);
}

// word map for 16-half chunks: pair p=(c>>1)&7 -> word 8*(c>>4) + 2*(p&3) + (p>>2)
// => thread (g,tig) gets (a0,a2)/(b0,b1) fragments via one LDS.64 at word 8kt+2tig.

// ---------------------------------------------------------------------------
// Kernel 1: node projections, fp16 mma single pass.
// 128 nodes/block, 8 warps x 16 rows; both tables in one pass (nt 0..15 over
// stacked [Ws;Wt], B row = nt*8+g). Outputs f16 at pos3-permuted cols.
// ---------------------------------------------------------------------------
#define K1S 72

__global__ __launch_bounds__(256)
void node_proj_kernel(const float* __restrict__ x,
                      const float* __restrict__ Ws, const float* __restrict__ bs,
                      const float* __restrict__ Wt, const float* __restrict__ bt,
                      const float* __restrict__ be) {
    extern __shared__ uint32_t sm1[];
    uint32_t* sX = sm1;                  // 128 x 72 (f16x2 words)
    uint32_t* sW = sm1 + 128 * K1S;      // 128 x 72 ([Ws;Wt] f16x2)

    const int tid = threadIdx.x;
    const int warp = tid >> 5, lane = tid & 31, g = lane >> 2, tig = lane & 3;
    const int m0 = blockIdx.x * 128;

    // stage X: 128 rows x 32 float4 -> f16x2 word map
#pragma unroll
    for (int i = 0; i < 16; i++) {
        int idx = i * 256 + tid;
        int r = idx >> 5, c4 = (idx & 31) * 4;
        float4 v = make_float4(0.f, 0.f, 0.f, 0.f);
        if (m0 + r < NN) v = *(const float4*)(x + (size_t)(m0 + r) * 128 + c4);
        int p1 = (c4 >> 1) & 7;
        int w1 = ((c4 >> 4) << 3) + 2 * (p1 & 3) + (p1 >> 2);
        int p2 = ((c4 + 2) >> 1) & 7;
        int w2 = (((c4 + 2) >> 4) << 3) + 2 * (p2 & 3) + (p2 >> 2);
        sX[r * K1S + w1] = pack_h2(v.x, v.y);
        sX[r * K1S + w2] = pack_h2(v.z, v.w);
    }
    // stage [Ws;Wt]: 2 x 64 rows x 32 float4
#pragma unroll
    for (int i = 0; i < 16; i++) {
        int idx = i * 256 + tid;
        int table = idx >> 11;
        int rem = idx & 2047;
        int r = rem >> 5, c4 = (rem & 31) * 4;
        const float* W = table ? Wt : Ws;
        float4 v = *(const float4*)(W + r * 128 + c4);
        int p1 = (c4 >> 1) & 7;
        int w1 = ((c4 >> 4) << 3) + 2 * (p1 & 3) + (p1 >> 2);
        int p2 = ((c4 + 2) >> 1) & 7;
        int w2 = (((c4 + 2) >> 4) << 3) + 2 * (p2 & 3) + (p2 >> 2);
        sW[(table * 64 + r) * K1S + w1] = pack_h2(v.x, v.y);
        sW[(table * 64 + r) * K1S + w2] = pack_h2(v.z, v.w);
    }
    __syncthreads();

    const int lr0 = warp * 16 + g;
    const uint32_t* A0 = sX + lr0 * K1S;
    const uint32_t* A1 = A0 + 8 * K1S;
    const int gr0 = m0 + lr0;

    float C[16][4];
#pragma unroll
    for (int nt = 0; nt < 16; nt++) { C[nt][0] = C[nt][1] = C[nt][2] = C[nt][3] = 0.f; }

#pragma unroll
    for (int kt = 0; kt < 8; kt++) {
        const int base = 8 * kt + 2 * tig;
        uint2 a0 = *(const uint2*)(A0 + base);   // (a0, a2)
        uint2 a1 = *(const uint2*)(A1 + base);   // (a1, a3)
#pragma unroll
        for (int nt = 0; nt < 16; nt++) {
            uint2 b = *(const uint2*)(sW + (nt * 8 + g) * K1S + base);
            mma16(C[nt], a0.x, a1.x, a0.y, a1.y, b.x, b.y);
        }
    }

#pragma unroll
    for (int nt = 0; nt < 16; nt++) {
        const int t = nt >> 3, ntl = nt & 7;
        const int c = ntl * 8 + 2 * tig;               // logical col (b=0)
        const int hp = 16 * tig + 2 * ntl;             // pos3 half-offset
        float bias0, bias1;
        if (t == 0) { bias0 = bs[c] + be[c]; bias1 = bs[c + 1] + be[c + 1]; }
        else        { bias0 = bt[c];         bias1 = bt[c + 1]; }
        __half* dst = t ? g_xt : g_xs;
        if (gr0 < NN) {
            *(uint32_t*)(dst + (size_t)gr0 * 64 + hp) =
                pack_h2(C[nt][0] + bias0, C[nt][1] + bias1);
        }
        if (gr0 + 8 < NN) {
            *(uint32_t*)(dst + (size_t)(gr0 + 8) * 64 + hp) =
                pack_h2(C[nt][2] + bias0, C[nt][3] + bias1);
        }
    }
}

// ---------------------------------------------------------------------------
// Kernel 2: fused edge MLP — fp16 m16n8k16, barrier-free per-warp pipeline.
// GELU via tanh.approx; output stores .cs (evict-first, keeps gather tables
// L2-resident). Otherwise identical to R12.
// ---------------------------------------------------------------------------
#define EAS 72
#define WSTR 40

__global__ __launch_bounds__(256, 2)
void edge_mlp_kernel(const float* __restrict__ ea,
                     const int* __restrict__ eidx,
                     const float* __restrict__ We,
                     const float* __restrict__ W1,
                     const float* __restrict__ b1,
                     float* __restrict__ out) {
    extern __shared__ uint32_t sm2[];
    uint32_t* sEA = sm2;                       // 256 x 72
    uint32_t* sWe = sm2 + 256 * EAS;           // 64 x 40 (f16x2 words)
    uint32_t* sW1 = sWe + 64 * WSTR;           // 64 x 40
    int* sSrc = (int*)(sW1 + 64 * WSTR);       // 256
    int* sTgt = sSrc + 256;                    // 256
    float* sB1 = (float*)(sTgt + 256);         // 64

    const int tid = threadIdx.x;
    const int warp = tid >> 5, lane = tid & 31, g = lane >> 2, tig = lane & 3;

    // ---- stage weights ONCE as f16x2 (word map; W1 rows permuted) ----
#pragma unroll
    for (int i = 0; i < 8; i++) {
        int idx = i * 256 + tid;               // 2048 float4 over both tables
        int table = idx >> 10;
        int rem = idx & 1023;
        int r = rem >> 4, c4 = (rem & 15) * 4;
        const float* W = table ? W1 : We;
        uint32_t* dst = table ? sW1 : sWe;
        int rp = table
               ? ((r & 0x31) | ((r & 0x2) << 2) | ((r & 0x8) >> 1) | ((r & 0x4) >> 1))
               : r;
        float4 v = *(const float4*)(W + r * 64 + c4);
        int p1 = (c4 >> 1) & 7;
        int w1 = ((c4 >> 4) << 3) + 2 * (p1 & 3) + (p1 >> 2);
        int p2 = ((c4 + 2) >> 1) & 7;
        int w2 = (((c4 + 2) >> 4) << 3) + 2 * (p2 & 3) + (p2 >> 2);
        dst[rp * WSTR + w1] = pack_h2(v.x, v.y);
        dst[rp * WSTR + w2] = pack_h2(v.z, v.w);
    }
    if (tid < 64) sB1[tid] = b1[tid];
    __syncthreads();   // weights/bias visible; after this, warps are independent

    const int rb = warp * 32 + g;              // row slots: rb, rb+8, rb+16, rb+24
    uint32_t* A0 = sEA + rb * EAS;
    uint32_t* A1 = A0 + 8 * EAS;
    uint32_t* A2 = A0 + 16 * EAS;
    uint32_t* A3 = A0 + 24 * EAS;

    const uint32_t eaRowAddr = smem_u32(sEA) + (uint32_t)(warp * 32) * EAS * 4;
    const int wg0 = blockIdx.x * 8 + warp;     // global warp id

    // ---- prologue: prefetch EA + indices for first tile ----
    int rs = 0, rt = 0;
    if (wg0 < NTG) {
        const float* gsrc = ea + (size_t)wg0 * 32 * 64;
#pragma unroll
        for (int i = 0; i < 16; i++) {
            int idx = i * 32 + lane;
            int r = idx >> 4, c4 = (idx & 15) << 2;
            uint32_t dst = eaRowAddr + (uint32_t)(r * EAS + c4) * 4;
            asm volatile("cp.async.cg.shared.global [%0], [%1], 16;"
                         :: "r"(dst), "l"(gsrc + r * 64 + c4) : "memory");
        }
        rs = eidx[(size_t)wg0 * 32 + lane];
        rt = eidx[NE + (size_t)wg0 * 32 + lane];
    }
    asm volatile("cp.async.commit_group;" ::: "memory");

    for (int tile = wg0; tile < NTG; tile += WS) {
        const long long e0 = (long long)tile * 32;

        sSrc[warp * 32 + lane] = min(max(rs, 0), NN - 1);
        sTgt[warp * 32 + lane] = min(max(rt, 0), NN - 1);
        if (tile + WS < NTG) {
            rs = eidx[(size_t)(tile + WS) * 32 + lane];
            rt = eidx[NE + (size_t)(tile + WS) * 32 + lane];
        }
        asm volatile("cp.async.wait_group 0;" ::: "memory");
        __syncwarp();

        // ---- stage 1: H = EA @ We^T  (f32 pairs -> f16x2 at consumption) ----
        float C[2][8][4];
#pragma unroll
        for (int s = 0; s < 2; s++)
#pragma unroll
            for (int nt = 0; nt < 8; nt++) { C[s][nt][0] = C[s][nt][1] = C[s][nt][2] = C[s][nt][3] = 0.f; }

#pragma unroll
        for (int kt = 0; kt < 4; kt++) {
            const int base = 16 * kt + 2 * tig;
            float2 l0 = *(const float2*)(A0 + base), h0 = *(const float2*)(A0 + base + 8);
            float2 l1 = *(const float2*)(A1 + base), h1 = *(const float2*)(A1 + base + 8);
            float2 l2 = *(const float2*)(A2 + base), h2 = *(const float2*)(A2 + base + 8);
            float2 l3 = *(const float2*)(A3 + base), h3 = *(const float2*)(A3 + base + 8);
            uint32_t a00 = pack_h2(l0.x, l0.y), a02 = pack_h2(h0.x, h0.y);
            uint32_t a01 = pack_h2(l1.x, l1.y), a03 = pack_h2(h1.x, h1.y);
            uint32_t a10 = pack_h2(l2.x, l2.y), a12 = pack_h2(h2.x, h2.y);
            uint32_t a11 = pack_h2(l3.x, l3.y), a13 = pack_h2(h3.x, h3.y);
#pragma unroll
            for (int nt = 0; nt < 8; nt++) {
                uint2 b = *(const uint2*)(sWe + (nt * 8 + g) * WSTR + 8 * kt + 2 * tig);
                mma16(C[0][nt], a00, a01, a02, a03, b.x, b.y);
                mma16(C[1][nt], a10, a11, a12, a13, b.x, b.y);
            }
        }

        // ---- gather (f16 tables, pos3: 2x LDG.128 per row per table) + GELU ----
#pragma unroll
        for (int s = 0; s < 4; s++) {
            const int row = rb + 8 * s;
            const int h = s >> 1, pb = (s & 1) * 2;
            const __half* xs = g_xs + (size_t)sSrc[row] * 64 + tig * 16;
            const __half* xt = g_xt + (size_t)sTgt[row] * 64 + tig * 16;
            uint4 pa = *(const uint4*)xs;          // halves 0..7  -> nt 0..3
            uint4 pbv = *(const uint4*)(xs + 8);   // halves 8..15 -> nt 4..7
            uint4 qa = *(const uint4*)xt;
            uint4 qb = *(const uint4*)(xt + 8);
            const __half2* ph = (const __half2*)&pa;
            const __half2* ph2 = (const __half2*)&pbv;
            const __half2* qh = (const __half2*)&qa;
            const __half2* qh2 = (const __half2*)&qb;
#pragma unroll
            for (int i = 0; i < 4; i++) {
                float2 px0 = __half22float2(2 * i < 4 ? ph[2 * i] : ph2[2 * i - 4]);
                float2 px1 = __half22float2(2 * i + 1 < 4 ? ph[2 * i + 1] : ph2[2 * i - 3]);
                float2 qx0 = __half22float2(2 * i < 4 ? qh[2 * i] : qh2[2 * i - 4]);
                float2 qx1 = __half22float2(2 * i + 1 < 4 ? qh[2 * i + 1] : qh2[2 * i - 3]);
                float v0 = C[h][2 * i + 0][pb + 0] + px0.x + qx0.x;
                float v1 = C[h][2 * i + 0][pb + 1] + px0.y + qx0.y;
                float v2 = C[h][2 * i + 1][pb + 0] + px1.x + qx1.x;
                float v3 = C[h][2 * i + 1][pb + 1] + px1.y + qx1.y;
                uint2 w;
                w.x = pack_h2(gelu_tanh(v0), gelu_tanh(v1));
                w.y = pack_h2(gelu_tanh(v2), gelu_tanh(v3));
                *(uint2*)(sEA + row * EAS + 8 * i + 2 * tig) = w;
            }
        }
        __syncwarp();  // H rows are warp-private

        // ---- stage 2: OUT = H @ W1p^T (N permuted) ----
#pragma unroll
        for (int s = 0; s < 2; s++)
#pragma unroll
            for (int nt = 0; nt < 8; nt++) { C[s][nt][0] = C[s][nt][1] = C[s][nt][2] = C[s][nt][3] = 0.f; }

#pragma unroll
        for (int kt = 0; kt < 4; kt++) {
            const int base = 8 * kt + 2 * tig;
            uint2 q0 = *(const uint2*)(A0 + base);
            uint2 q1 = *(const uint2*)(A1 + base);
            uint2 q2 = *(const uint2*)(A2 + base);
            uint2 q3 = *(const uint2*)(A3 + base);
#pragma unroll
            for (int nt = 0; nt < 8; nt++) {
                uint2 b = *(const uint2*)(sW1 + (nt * 8 + g) * WSTR + base);
                mma16(C[0][nt], q0.x, q1.x, q0.y, q1.y, b.x, b.y);
                mma16(C[1][nt], q2.x, q3.x, q2.y, q3.y, b.x, b.y);
            }
        }

        // ---- prefetch next tile's EA ----
        if (tile + WS < NTG) {
            const float* gsrc = ea + (size_t)(tile + WS) * 32 * 64;
#pragma unroll
            for (int i = 0; i < 16; i++) {
                int idx = i * 32 + lane;
                int r = idx >> 4, c4 = (idx & 15) << 2;
                uint32_t dst = eaRowAddr + (uint32_t)(r * EAS + c4) * 4;
                asm volatile("cp.async.cg.shared.global [%0], [%1], 16;"
                             :: "r"(dst), "l"(gsrc + r * 64 + c4) : "memory");
            }
        }
        asm volatile("cp.async.commit_group;" ::: "memory");

        // ---- epilogue: +b1, STG.128 .cs at logical cols i*16 + tig*4 ----
        float4 bia[4];
#pragma unroll
        for (int i = 0; i < 4; i++) bia[i] = *(const float4*)(sB1 + i * 16 + tig * 4);
#pragma unroll
        for (int s = 0; s < 4; s++) {
            const int h = s >> 1, pb = (s & 1) * 2;
            float* orow = out + (size_t)(e0 + g + 8 * s) * 64 + tig * 4;
#pragma unroll
            for (int i = 0; i < 4; i++) {
                float vx = C[h][2 * i + 0][pb + 0] + bia[i].x;
                float vy = C[h][2 * i + 0][pb + 1] + bia[i].y;
                float vz = C[h][2 * i + 1][pb + 0] + bia[i].z;
                float vw = C[h][2 * i + 1][pb + 1] + bia[i].w;
                asm volatile("st.global.cs.v4.f32 [%0], {%1,%2,%3,%4};"
                             :: "l"(orow + i * 16), "f"(vx), "f"(vy), "f"(vz), "f"(vw)
                             : "memory");
            }
        }
    }
}

extern "C" void kernel_launch(void* const* d_in, const int* in_sizes, int n_in,
                              void* d_out, int out_size) {
    const float* x   = (const float*)d_in[0];
    const int*   ei  = (const int*)d_in[1];     // int32 (JAX default x64-disabled)
    const float* ea  = (const float*)d_in[2];
    const float* We  = (const float*)d_in[3];
    const float* be  = (const float*)d_in[4];
    const float* Ws  = (const float*)d_in[5];
    const float* bs  = (const float*)d_in[6];
    const float* Wt  = (const float*)d_in[7];
    const float* bt  = (const float*)d_in[8];
    const float* W1  = (const float*)d_in[9];
    const float* b1  = (const float*)d_in[10];
    float* out = (float*)d_out;

    const size_t smem1 = (size_t)(128 * K1S + 128 * K1S) * 4;                      // ~74 KB
    const size_t smem2 = (size_t)(256 * EAS + 2 * 64 * WSTR + 512 + 64 + 16) * 4;  // ~94 KB
    cudaFuncSetAttribute(node_proj_kernel, cudaFuncAttributeMaxDynamicSharedMemorySize, (int)smem1);
    cudaFuncSetAttribute(edge_mlp_kernel,  cudaFuncAttributeMaxDynamicSharedMemorySize, (int)smem2);

    node_proj_kernel<<<(NN + 127) / 128, 256, smem1>>>(x, Ws, bs, Wt, bt, be);
    edge_mlp_kernel<<<PGRID, 256, smem2>>>(ea, ei, We, W1, b1, out);
}

// round 14
// speedup vs baseline: 1.7428x; 1.0475x over previous
#include <cuda_runtime.h>
#include <cuda_fp16.h>
#include <cstdint>
#include <cstddef>

#define NE 1000000
#define NN 50000
#define NTG 31250                      // 32-edge groups (NE divisible by 32)
#define PGRID 296
#define WS (PGRID * 8)                 // total warps = edge tile stride
#define NTN ((NN + 127) / 128)         // 391 node tiles

// node projections stored as f16, COLUMN-PERMUTED with pos3:
// logical feature c = 8nt + 2tig + b lives at half-index pos3(c) = 16*tig + 2*nt + b.
__device__ __half g_xs[(size_t)NN * 64];
__device__ __half g_xt[(size_t)NN * 64];
__device__ unsigned int g_bar;         // monotonic device barrier counter

__device__ __forceinline__ uint32_t smem_u32(const void* p) {
    uint32_t a;
    asm("{ .reg .u64 t; cvta.to.shared.u64 t, %1; cvt.u32.u64 %0, t; }" : "=r"(a) : "l"(p));
    return a;
}

__device__ __forceinline__ uint32_t pack_h2(float x, float y) {
    __half2 h = __float22half2_rn(make_float2(x, y));   // lo=x, hi=y
    return *reinterpret_cast<uint32_t*>(&h);
}

// fp16 m16n8k16 with fp32 accumulate
__device__ __forceinline__ void mma16(float c[4],
                                      uint32_t a0, uint32_t a1, uint32_t a2, uint32_t a3,
                                      uint32_t b0, uint32_t b1) {
    asm volatile(
        "mma.sync.aligned.m16n8k16.row.col.f32.f16.f16.f32 "
        "{%0,%1,%2,%3}, {%4,%5,%6,%7}, {%8,%9}, {%10,%11,%12,%13};\n"
        : "=f"(c[0]), "=f"(c[1]), "=f"(c[2]), "=f"(c[3])
        : "r"(a0), "r"(a1), "r"(a2), "r"(a3), "r"(b0), "r"(b1),
          "f"(c[0]), "f"(c[1]), "f"(c[2]), "f"(c[3]));
}

// jax.nn.gelu approximate via MUFU.TANH: 0.5v(1+tanh(0.79788456(v+0.044715v^3)))
__device__ __forceinline__ float gelu_tanh(float v) {
    float u = v * fmaf(0.035677408136300125f, v * v, 0.7978845608028654f);
    float t;
    asm("tanh.approx.f32 %0, %1;" : "=f"(t) : "f"(u));
    float hv = 0.5f * v;
    return fmaf(hv, t, hv);
}

// word map for 16-half chunks: pair p=(c>>1)&7 -> word 8*(c>>4) + 2*(p&3) + (p>>2)

#define K1S 72
#define EAS 72
#define WSTR 40
// smem words: max(phaseA 128*72+128*72 = 18432, phaseB 256*72+2*64*40+512+64+16 = 24144)
#define SMW 24144

__global__ __launch_bounds__(256, 2)
void fused_kernel(const float* __restrict__ x,
                  const float* __restrict__ Ws, const float* __restrict__ bs,
                  const float* __restrict__ Wt, const float* __restrict__ bt,
                  const float* __restrict__ be,
                  const float* __restrict__ ea,
                  const int* __restrict__ eidx,
                  const float* __restrict__ We,
                  const float* __restrict__ W1,
                  const float* __restrict__ b1,
                  float* __restrict__ out) {
    extern __shared__ uint32_t sm[];
    const int tid = threadIdx.x;
    const int warp = tid >> 5, lane = tid & 31, g = lane >> 2, tig = lane & 3;

    // =======================================================================
    // PHASE A: node projections (grid-strided 128-node tiles)
    // =======================================================================
    {
        uint32_t* sX = sm;                   // 128 x 72
        uint32_t* sW = sm + 128 * K1S;       // 128 x 72 ([Ws;Wt])

        // stage [Ws;Wt] once per CTA
#pragma unroll
        for (int i = 0; i < 16; i++) {
            int idx = i * 256 + tid;
            int table = idx >> 11;
            int rem = idx & 2047;
            int r = rem >> 5, c4 = (rem & 31) * 4;
            const float* W = table ? Wt : Ws;
            float4 v = *(const float4*)(W + r * 128 + c4);
            int p1 = (c4 >> 1) & 7;
            int w1 = ((c4 >> 4) << 3) + 2 * (p1 & 3) + (p1 >> 2);
            int p2 = ((c4 + 2) >> 1) & 7;
            int w2 = (((c4 + 2) >> 4) << 3) + 2 * (p2 & 3) + (p2 >> 2);
            sW[(table * 64 + r) * K1S + w1] = pack_h2(v.x, v.y);
            sW[(table * 64 + r) * K1S + w2] = pack_h2(v.z, v.w);
        }

        for (int nt0 = blockIdx.x; nt0 < NTN; nt0 += PGRID) {
            const int m0 = nt0 * 128;
            __syncthreads();   // protect sX from previous tile's readers
#pragma unroll
            for (int i = 0; i < 16; i++) {
                int idx = i * 256 + tid;
                int r = idx >> 5, c4 = (idx & 31) * 4;
                float4 v = make_float4(0.f, 0.f, 0.f, 0.f);
                if (m0 + r < NN) v = *(const float4*)(x + (size_t)(m0 + r) * 128 + c4);
                int p1 = (c4 >> 1) & 7;
                int w1 = ((c4 >> 4) << 3) + 2 * (p1 & 3) + (p1 >> 2);
                int p2 = ((c4 + 2) >> 1) & 7;
                int w2 = (((c4 + 2) >> 4) << 3) + 2 * (p2 & 3) + (p2 >> 2);
                sX[r * K1S + w1] = pack_h2(v.x, v.y);
                sX[r * K1S + w2] = pack_h2(v.z, v.w);
            }
            __syncthreads();

            const int lr0 = warp * 16 + g;
            const uint32_t* A0 = sX + lr0 * K1S;
            const uint32_t* A1 = A0 + 8 * K1S;
            const int gr0 = m0 + lr0;

            float C[16][4];
#pragma unroll
            for (int nt = 0; nt < 16; nt++) { C[nt][0] = C[nt][1] = C[nt][2] = C[nt][3] = 0.f; }

#pragma unroll
            for (int kt = 0; kt < 8; kt++) {
                const int base = 8 * kt + 2 * tig;
                uint2 a0 = *(const uint2*)(A0 + base);   // (a0, a2)
                uint2 a1 = *(const uint2*)(A1 + base);   // (a1, a3)
#pragma unroll
                for (int nt = 0; nt < 16; nt++) {
                    uint2 b = *(const uint2*)(sW + (nt * 8 + g) * K1S + base);
                    mma16(C[nt], a0.x, a1.x, a0.y, a1.y, b.x, b.y);
                }
            }

#pragma unroll
            for (int nt = 0; nt < 16; nt++) {
                const int t = nt >> 3, ntl = nt & 7;
                const int c = ntl * 8 + 2 * tig;               // logical col (b=0)
                const int hp = 16 * tig + 2 * ntl;             // pos3 half-offset
                float bias0, bias1;
                if (t == 0) { bias0 = bs[c] + be[c]; bias1 = bs[c + 1] + be[c + 1]; }
                else        { bias0 = bt[c];         bias1 = bt[c + 1]; }
                __half* dst = t ? g_xt : g_xs;
                if (gr0 < NN) {
                    *(uint32_t*)(dst + (size_t)gr0 * 64 + hp) =
                        pack_h2(C[nt][0] + bias0, C[nt][1] + bias1);
                }
                if (gr0 + 8 < NN) {
                    *(uint32_t*)(dst + (size_t)(gr0 + 8) * 64 + hp) =
                        pack_h2(C[nt][2] + bias0, C[nt][3] + bias1);
                }
            }
        }
    }

    // =======================================================================
    // device-wide barrier (grid == 2 CTAs/SM == fully resident; replay-safe
    // monotonic counter: each launch adds exactly PGRID arrivals)
    // =======================================================================
    __syncthreads();
    if (tid == 0) {
        __threadfence();
        unsigned a;
        asm volatile("atom.global.add.u32 %0, [%1], 1;" : "=r"(a) : "l"(&g_bar) : "memory");
        const unsigned target = (a / PGRID) * PGRID + PGRID;
        unsigned cur;
        do {
            asm volatile("ld.acquire.gpu.u32 %0, [%1];" : "=r"(cur) : "l"(&g_bar) : "memory");
        } while (cur < target);
    }
    __syncthreads();

    // =======================================================================
    // PHASE B: fused edge MLP (R13 pipeline)
    // =======================================================================
    uint32_t* sEA = sm;                        // 256 x 72
    uint32_t* sWe = sm + 256 * EAS;            // 64 x 40 (f16x2 words)
    uint32_t* sW1 = sWe + 64 * WSTR;           // 64 x 40
    int* sSrc = (int*)(sW1 + 64 * WSTR);       // 256
    int* sTgt = sSrc + 256;                    // 256
    float* sB1 = (float*)(sTgt + 256);         // 64

    // ---- stage weights ONCE as f16x2 (word map; W1 rows permuted) ----
#pragma unroll
    for (int i = 0; i < 8; i++) {
        int idx = i * 256 + tid;               // 2048 float4 over both tables
        int table = idx >> 10;
        int rem = idx & 1023;
        int r = rem >> 4, c4 = (rem & 15) * 4;
        const float* W = table ? W1 : We;
        uint32_t* dst = table ? sW1 : sWe;
        int rp = table
               ? ((r & 0x31) | ((r & 0x2) << 2) | ((r & 0x8) >> 1) | ((r & 0x4) >> 1))
               : r;
        float4 v = *(const float4*)(W + r * 64 + c4);
        int p1 = (c4 >> 1) & 7;
        int w1 = ((c4 >> 4) << 3) + 2 * (p1 & 3) + (p1 >> 2);
        int p2 = ((c4 + 2) >> 1) & 7;
        int w2 = (((c4 + 2) >> 4) << 3) + 2 * (p2 & 3) + (p2 >> 2);
        dst[rp * WSTR + w1] = pack_h2(v.x, v.y);
        dst[rp * WSTR + w2] = pack_h2(v.z, v.w);
    }
    if (tid < 64) sB1[tid] = b1[tid];
    __syncthreads();   // weights/bias visible; after this, warps are independent

    const int rb = warp * 32 + g;              // row slots: rb, rb+8, rb+16, rb+24
    uint32_t* A0 = sEA + rb * EAS;
    uint32_t* A1 = A0 + 8 * EAS;
    uint32_t* A2 = A0 + 16 * EAS;
    uint32_t* A3 = A0 + 24 * EAS;

    const uint32_t eaRowAddr = smem_u32(sEA) + (uint32_t)(warp * 32) * EAS * 4;
    const int wg0 = blockIdx.x * 8 + warp;     // global warp id

    // ---- prologue: prefetch EA + indices for first tile ----
    int rs = 0, rt = 0;
    if (wg0 < NTG) {
        const float* gsrc = ea + (size_t)wg0 * 32 * 64;
#pragma unroll
        for (int i = 0; i < 16; i++) {
            int idx = i * 32 + lane;
            int r = idx >> 4, c4 = (idx & 15) << 2;
            uint32_t dst = eaRowAddr + (uint32_t)(r * EAS + c4) * 4;
            asm volatile("cp.async.cg.shared.global [%0], [%1], 16;"
                         :: "r"(dst), "l"(gsrc + r * 64 + c4) : "memory");
        }
        rs = eidx[(size_t)wg0 * 32 + lane];
        rt = eidx[NE + (size_t)wg0 * 32 + lane];
    }
    asm volatile("cp.async.commit_group;" ::: "memory");

    for (int tile = wg0; tile < NTG; tile += WS) {
        const long long e0 = (long long)tile * 32;

        sSrc[warp * 32 + lane] = min(max(rs, 0), NN - 1);
        sTgt[warp * 32 + lane] = min(max(rt, 0), NN - 1);
        if (tile + WS < NTG) {
            rs = eidx[(size_t)(tile + WS) * 32 + lane];
            rt = eidx[NE + (size_t)(tile + WS) * 32 + lane];
        }
        asm volatile("cp.async.wait_group 0;" ::: "memory");
        __syncwarp();

        // ---- stage 1: H = EA @ We^T  (f32 pairs -> f16x2 at consumption) ----
        float C[2][8][4];
#pragma unroll
        for (int s = 0; s < 2; s++)
#pragma unroll
            for (int nt = 0; nt < 8; nt++) { C[s][nt][0] = C[s][nt][1] = C[s][nt][2] = C[s][nt][3] = 0.f; }

#pragma unroll
        for (int kt = 0; kt < 4; kt++) {
            const int base = 16 * kt + 2 * tig;
            float2 l0 = *(const float2*)(A0 + base), h0 = *(const float2*)(A0 + base + 8);
            float2 l1 = *(const float2*)(A1 + base), h1 = *(const float2*)(A1 + base + 8);
            float2 l2 = *(const float2*)(A2 + base), h2 = *(const float2*)(A2 + base + 8);
            float2 l3 = *(const float2*)(A3 + base), h3 = *(const float2*)(A3 + base + 8);
            uint32_t a00 = pack_h2(l0.x, l0.y), a02 = pack_h2(h0.x, h0.y);
            uint32_t a01 = pack_h2(l1.x, l1.y), a03 = pack_h2(h1.x, h1.y);
            uint32_t a10 = pack_h2(l2.x, l2.y), a12 = pack_h2(h2.x, h2.y);
            uint32_t a11 = pack_h2(l3.x, l3.y), a13 = pack_h2(h3.x, h3.y);
#pragma unroll
            for (int nt = 0; nt < 8; nt++) {
                uint2 b = *(const uint2*)(sWe + (nt * 8 + g) * WSTR + 8 * kt + 2 * tig);
                mma16(C[0][nt], a00, a01, a02, a03, b.x, b.y);
                mma16(C[1][nt], a10, a11, a12, a13, b.x, b.y);
            }
        }

        // ---- gather (f16 tables, pos3: 2x LDG.128 per row per table) + GELU ----
#pragma unroll
        for (int s = 0; s < 4; s++) {
            const int row = rb + 8 * s;
            const int h = s >> 1, pb = (s & 1) * 2;
            const __half* xs = g_xs + (size_t)sSrc[row] * 64 + tig * 16;
            const __half* xt = g_xt + (size_t)sTgt[row] * 64 + tig * 16;
            uint4 pa = *(const uint4*)xs;          // halves 0..7  -> nt 0..3
            uint4 pbv = *(const uint4*)(xs + 8);   // halves 8..15 -> nt 4..7
            uint4 qa = *(const uint4*)xt;
            uint4 qb = *(const uint4*)(xt + 8);
            const __half2* ph = (const __half2*)&pa;
            const __half2* ph2 = (const __half2*)&pbv;
            const __half2* qh = (const __half2*)&qa;
            const __half2* qh2 = (const __half2*)&qb;
#pragma unroll
            for (int i = 0; i < 4; i++) {
                float2 px0 = __half22float2(2 * i < 4 ? ph[2 * i] : ph2[2 * i - 4]);
                float2 px1 = __half22float2(2 * i + 1 < 4 ? ph[2 * i + 1] : ph2[2 * i - 3]);
                float2 qx0 = __half22float2(2 * i < 4 ? qh[2 * i] : qh2[2 * i - 4]);
                float2 qx1 = __half22float2(2 * i + 1 < 4 ? qh[2 * i + 1] : qh2[2 * i - 3]);
                float v0 = C[h][2 * i + 0][pb + 0] + px0.x + qx0.x;
                float v1 = C[h][2 * i + 0][pb + 1] + px0.y + qx0.y;
                float v2 = C[h][2 * i + 1][pb + 0] + px1.x + qx1.x;
                float v3 = C[h][2 * i + 1][pb + 1] + px1.y + qx1.y;
                uint2 w;
                w.x = pack_h2(gelu_tanh(v0), gelu_tanh(v1));
                w.y = pack_h2(gelu_tanh(v2), gelu_tanh(v3));
                *(uint2*)(sEA + row * EAS + 8 * i + 2 * tig) = w;
            }
        }
        __syncwarp();  // H rows are warp-private

        // ---- stage 2: OUT = H @ W1p^T (N permuted) ----
#pragma unroll
        for (int s = 0; s < 2; s++)
#pragma unroll
            for (int nt = 0; nt < 8; nt++) { C[s][nt][0] = C[s][nt][1] = C[s][nt][2] = C[s][nt][3] = 0.f; }

#pragma unroll
        for (int kt = 0; kt < 4; kt++) {
            const int base = 8 * kt + 2 * tig;
            uint2 q0 = *(const uint2*)(A0 + base);
            uint2 q1 = *(const uint2*)(A1 + base);
            uint2 q2 = *(const uint2*)(A2 + base);
            uint2 q3 = *(const uint2*)(A3 + base);
#pragma unroll
            for (int nt = 0; nt < 8; nt++) {
                uint2 b = *(const uint2*)(sW1 + (nt * 8 + g) * WSTR + base);
                mma16(C[0][nt], q0.x, q1.x, q0.y, q1.y, b.x, b.y);
                mma16(C[1][nt], q2.x, q3.x, q2.y, q3.y, b.x, b.y);
            }
        }

        // ---- prefetch next tile's EA ----
        if (tile + WS < NTG) {
            const float* gsrc = ea + (size_t)(tile + WS) * 32 * 64;
#pragma unroll
            for (int i = 0; i < 16; i++) {
                int idx = i * 32 + lane;
                int r = idx >> 4, c4 = (idx & 15) << 2;
                uint32_t dst = eaRowAddr + (uint32_t)(r * EAS + c4) * 4;
                asm volatile("cp.async.cg.shared.global [%0], [%1], 16;"
                             :: "r"(dst), "l"(gsrc + r * 64 + c4) : "memory");
            }
        }
        asm volatile("cp.async.commit_group;" ::: "memory");

        // ---- epilogue: +b1, STG.128 .cs at logical cols i*16 + tig*4 ----
        float4 bia[4];
#pragma unroll
        for (int i = 0; i < 4; i++) bia[i] = *(const float4*)(sB1 + i * 16 + tig * 4);
#pragma unroll
        for (int s = 0; s < 4; s++) {
            const int h = s >> 1, pb = (s & 1) * 2;
            float* orow = out + (size_t)(e0 + g + 8 * s) * 64 + tig * 4;
#pragma unroll
            for (int i = 0; i < 4; i++) {
                float vx = C[h][2 * i + 0][pb + 0] + bia[i].x;
                float vy = C[h][2 * i + 0][pb + 1] + bia[i].y;
                float vz = C[h][2 * i + 1][pb + 0] + bia[i].z;
                float vw = C[h][2 * i + 1][pb + 1] + bia[i].w;
                asm volatile("st.global.cs.v4.f32 [%0], {%1,%2,%3,%4};"
                             :: "l"(orow + i * 16), "f"(vx), "f"(vy), "f"(vz), "f"(vw)
                             : "memory");
            }
        }
    }
}

extern "C" void kernel_launch(void* const* d_in, const int* in_sizes, int n_in,
                              void* d_out, int out_size) {
    const float* x   = (const float*)d_in[0];
    const int*   ei  = (const int*)d_in[1];     // int32 (JAX default x64-disabled)
    const float* ea  = (const float*)d_in[2];
    const float* We  = (const float*)d_in[3];
    const float* be  = (const float*)d_in[4];
    const float* Ws  = (const float*)d_in[5];
    const float* bs  = (const float*)d_in[6];
    const float* Wt  = (const float*)d_in[7];
    const float* bt  = (const float*)d_in[8];
    const float* W1  = (const float*)d_in[9];
    const float* b1  = (const float*)d_in[10];
    float* out = (float*)d_out;

    const size_t smem = (size_t)SMW * 4;   // ~94 KB
    cudaFuncSetAttribute(fused_kernel, cudaFuncAttributeMaxDynamicSharedMemorySize, (int)smem);

    fused_kernel<<<PGRID, 256, smem>>>(x, Ws, bs, Wt, bt, be, ea, ei, We, W1, b1, out);
}

// round 15
// speedup vs baseline: 1.7684x; 1.0147x over previous
#include <cuda_runtime.h>
#include <cuda_fp16.h>
#include <cstdint>
#include <cstddef>

#define NE 1000000
#define NN 50000
#define NTG 31250                      // 32-edge groups (NE divisible by 32)
#define PGRID 296
#define WS (PGRID * 8)                 // total warps
#define NTN (NN / 16)                  // 3125 16-node tiles (exact)

// node projections stored as f16, COLUMN-PERMUTED with pos3:
// logical feature c = 8nt + 2tig + b lives at half-index pos3(c) = 16*tig + 2*nt + b.
__device__ __half g_xs[(size_t)NN * 64];
__device__ __half g_xt[(size_t)NN * 64];
__device__ unsigned int g_bar;         // monotonic device barrier counter

__device__ __forceinline__ uint32_t smem_u32(const void* p) {
    uint32_t a;
    asm("{ .reg .u64 t; cvta.to.shared.u64 t, %1; cvt.u32.u64 %0, t; }" : "=r"(a) : "l"(p));
    return a;
}

__device__ __forceinline__ uint32_t pack_h2(float x, float y) {
    __half2 h = __float22half2_rn(make_float2(x, y));   // lo=x, hi=y
    return *reinterpret_cast<uint32_t*>(&h);
}

// fp16 m16n8k16 with fp32 accumulate
__device__ __forceinline__ void mma16(float c[4],
                                      uint32_t a0, uint32_t a1, uint32_t a2, uint32_t a3,
                                      uint32_t b0, uint32_t b1) {
    asm volatile(
        "mma.sync.aligned.m16n8k16.row.col.f32.f16.f16.f32 "
        "{%0,%1,%2,%3}, {%4,%5,%6,%7}, {%8,%9}, {%10,%11,%12,%13};\n"
        : "=f"(c[0]), "=f"(c[1]), "=f"(c[2]), "=f"(c[3])
        : "r"(a0), "r"(a1), "r"(a2), "r"(a3), "r"(b0), "r"(b1),
          "f"(c[0]), "f"(c[1]), "f"(c[2]), "f"(c[3]));
}

// jax.nn.gelu approximate via MUFU.TANH: 0.5v(1+tanh(0.79788456(v+0.044715v^3)))
__device__ __forceinline__ float gelu_tanh(float v) {
    float u = v * fmaf(0.035677408136300125f, v * v, 0.7978845608028654f);
    float t;
    asm("tanh.approx.f32 %0, %1;" : "=f"(t) : "f"(u));
    float hv = 0.5f * v;
    return fmaf(hv, t, hv);
}

// word map for 16-half chunks: pair p=(c>>1)&7 -> word 8*(c>>4) + 2*(p&3) + (p>>2)

#define K1S 72
#define EAS 72
#define WSTR 40
// smem words: max(phaseA 128*72+128*72 = 18432, phaseB 256*72+2*64*40+512+64+16 = 24144)
#define SMW 24144

__global__ __launch_bounds__(256, 2)
void fused_kernel(const float* __restrict__ x,
                  const float* __restrict__ Ws, const float* __restrict__ bs,
                  const float* __restrict__ Wt, const float* __restrict__ bt,
                  const float* __restrict__ be,
                  const float* __restrict__ ea,
                  const int* __restrict__ eidx,
                  const float* __restrict__ We,
                  const float* __restrict__ W1,
                  const float* __restrict__ b1,
                  float* __restrict__ out) {
    extern __shared__ uint32_t sm[];
    const int tid = threadIdx.x;
    const int warp = tid >> 5, lane = tid & 31, g = lane >> 2, tig = lane & 3;

    // =======================================================================
    // PHASE A: node projections — warp-granular 16-node tiles, no block
    // barriers in the loop. Each warp owns a private 16-row smem slice.
    // =======================================================================
    {
        uint32_t* sX = sm;                   // 128 x 72 (8 warps x 16 rows)
        uint32_t* sW = sm + 128 * K1S;       // 128 x 72 ([Ws;Wt])

        // stage [Ws;Wt] once per CTA (block-cooperative)
#pragma unroll
        for (int i = 0; i < 16; i++) {
            int idx = i * 256 + tid;
            int table = idx >> 11;
            int rem = idx & 2047;
            int r = rem >> 5, c4 = (rem & 31) * 4;
            const float* W = table ? Wt : Ws;
            float4 v = *(const float4*)(W + r * 128 + c4);
            int p1 = (c4 >> 1) & 7;
            int w1 = ((c4 >> 4) << 3) + 2 * (p1 & 3) + (p1 >> 2);
            int p2 = ((c4 + 2) >> 1) & 7;
            int w2 = (((c4 + 2) >> 4) << 3) + 2 * (p2 & 3) + (p2 >> 2);
            sW[(table * 64 + r) * K1S + w1] = pack_h2(v.x, v.y);
            sW[(table * 64 + r) * K1S + w2] = pack_h2(v.z, v.w);
        }
        __syncthreads();   // weights visible to all warps

        uint32_t* sXw = sX + warp * 16 * K1S;      // this warp's 16-row slice
        const uint32_t* A0 = sXw + g * K1S;
        const uint32_t* A1 = A0 + 8 * K1S;
        const int gw = blockIdx.x * 8 + warp;      // global warp id

        // column word offsets for this lane's float4 (c4 = lane*4)
        const int c4l = lane * 4;
        const int p1l = (c4l >> 1) & 7;
        const int w1l = ((c4l >> 4) << 3) + 2 * (p1l & 3) + (p1l >> 2);
        const int p2l = ((c4l + 2) >> 1) & 7;
        const int w2l = (((c4l + 2) >> 4) << 3) + 2 * (p2l & 3) + (p2l >> 2);

        for (int tile = gw; tile < NTN; tile += WS) {
            const int m0 = tile * 16;
            __syncwarp();    // protect slice from this warp's previous reads
#pragma unroll
            for (int r = 0; r < 16; r++) {
                float4 v = *(const float4*)(x + (size_t)(m0 + r) * 128 + c4l);
                sXw[r * K1S + w1l] = pack_h2(v.x, v.y);
                sXw[r * K1S + w2l] = pack_h2(v.z, v.w);
            }
            __syncwarp();

            float C[16][4];
#pragma unroll
            for (int nt = 0; nt < 16; nt++) { C[nt][0] = C[nt][1] = C[nt][2] = C[nt][3] = 0.f; }

#pragma unroll
            for (int kt = 0; kt < 8; kt++) {
                const int base = 8 * kt + 2 * tig;
                uint2 a0 = *(const uint2*)(A0 + base);   // (a0, a2)
                uint2 a1 = *(const uint2*)(A1 + base);   // (a1, a3)
#pragma unroll
                for (int nt = 0; nt < 16; nt++) {
                    uint2 b = *(const uint2*)(sW + (nt * 8 + g) * K1S + base);
                    mma16(C[nt], a0.x, a1.x, a0.y, a1.y, b.x, b.y);
                }
            }

            const int gr0 = m0 + g;    // rows gr0 and gr0+8 (always in range)
#pragma unroll
            for (int nt = 0; nt < 16; nt++) {
                const int t = nt >> 3, ntl = nt & 7;
                const int c = ntl * 8 + 2 * tig;               // logical col (b=0)
                const int hp = 16 * tig + 2 * ntl;             // pos3 half-offset
                float bias0, bias1;
                if (t == 0) { bias0 = bs[c] + be[c]; bias1 = bs[c + 1] + be[c + 1]; }
                else        { bias0 = bt[c];         bias1 = bt[c + 1]; }
                __half* dst = t ? g_xt : g_xs;
                *(uint32_t*)(dst + (size_t)gr0 * 64 + hp) =
                    pack_h2(C[nt][0] + bias0, C[nt][1] + bias1);
                *(uint32_t*)(dst + (size_t)(gr0 + 8) * 64 + hp) =
                    pack_h2(C[nt][2] + bias0, C[nt][3] + bias1);
            }
        }
    }

    // =======================================================================
    // device-wide barrier (grid == 2 CTAs/SM == fully resident; replay-safe
    // monotonic counter: each launch adds exactly PGRID arrivals)
    // =======================================================================
    __syncthreads();
    if (tid == 0) {
        __threadfence();
        unsigned a;
        asm volatile("atom.global.add.u32 %0, [%1], 1;" : "=r"(a) : "l"(&g_bar) : "memory");
        const unsigned target = (a / PGRID) * PGRID + PGRID;
        unsigned cur;
        do {
            asm volatile("ld.acquire.gpu.u32 %0, [%1];" : "=r"(cur) : "l"(&g_bar) : "memory");
        } while (cur < target);
    }
    __syncthreads();

    // =======================================================================
    // PHASE B: fused edge MLP (R13 pipeline, unchanged)
    // =======================================================================
    uint32_t* sEA = sm;                        // 256 x 72
    uint32_t* sWe = sm + 256 * EAS;            // 64 x 40 (f16x2 words)
    uint32_t* sW1 = sWe + 64 * WSTR;           // 64 x 40
    int* sSrc = (int*)(sW1 + 64 * WSTR);       // 256
    int* sTgt = sSrc + 256;                    // 256
    float* sB1 = (float*)(sTgt + 256);         // 64

    // ---- stage weights ONCE as f16x2 (word map; W1 rows permuted) ----
#pragma unroll
    for (int i = 0; i < 8; i++) {
        int idx = i * 256 + tid;               // 2048 float4 over both tables
        int table = idx >> 10;
        int rem = idx & 1023;
        int r = rem >> 4, c4 = (rem & 15) * 4;
        const float* W = table ? W1 : We;
        uint32_t* dst = table ? sW1 : sWe;
        int rp = table
               ? ((r & 0x31) | ((r & 0x2) << 2) | ((r & 0x8) >> 1) | ((r & 0x4) >> 1))
               : r;
        float4 v = *(const float4*)(W + r * 64 + c4);
        int p1 = (c4 >> 1) & 7;
        int w1 = ((c4 >> 4) << 3) + 2 * (p1 & 3) + (p1 >> 2);
        int p2 = ((c4 + 2) >> 1) & 7;
        int w2 = (((c4 + 2) >> 4) << 3) + 2 * (p2 & 3) + (p2 >> 2);
        dst[rp * WSTR + w1] = pack_h2(v.x, v.y);
        dst[rp * WSTR + w2] = pack_h2(v.z, v.w);
    }
    if (tid < 64) sB1[tid] = b1[tid];
    __syncthreads();   // weights/bias visible; after this, warps are independent

    const int rb = warp * 32 + g;              // row slots: rb, rb+8, rb+16, rb+24
    uint32_t* A0 = sEA + rb * EAS;
    uint32_t* A1 = A0 + 8 * EAS;
    uint32_t* A2 = A0 + 16 * EAS;
    uint32_t* A3 = A0 + 24 * EAS;

    const uint32_t eaRowAddr = smem_u32(sEA) + (uint32_t)(warp * 32) * EAS * 4;
    const int wg0 = blockIdx.x * 8 + warp;     // global warp id

    // ---- prologue: prefetch EA + indices for first tile ----
    int rs = 0, rt = 0;
    if (wg0 < NTG) {
        const float* gsrc = ea + (size_t)wg0 * 32 * 64;
#pragma unroll
        for (int i = 0; i < 16; i++) {
            int idx = i * 32 + lane;
            int r = idx >> 4, c4 = (idx & 15) << 2;
            uint32_t dst = eaRowAddr + (uint32_t)(r * EAS + c4) * 4;
            asm volatile("cp.async.cg.shared.global [%0], [%1], 16;"
                         :: "r"(dst), "l"(gsrc + r * 64 + c4) : "memory");
        }
        rs = eidx[(size_t)wg0 * 32 + lane];
        rt = eidx[NE + (size_t)wg0 * 32 + lane];
    }
    asm volatile("cp.async.commit_group;" ::: "memory");

    for (int tile = wg0; tile < NTG; tile += WS) {
        const long long e0 = (long long)tile * 32;

        sSrc[warp * 32 + lane] = min(max(rs, 0), NN - 1);
        sTgt[warp * 32 + lane] = min(max(rt, 0), NN - 1);
        if (tile + WS < NTG) {
            rs = eidx[(size_t)(tile + WS) * 32 + lane];
            rt = eidx[NE + (size_t)(tile + WS) * 32 + lane];
        }
        asm volatile("cp.async.wait_group 0;" ::: "memory");
        __syncwarp();

        // ---- stage 1: H = EA @ We^T  (f32 pairs -> f16x2 at consumption) ----
        float C[2][8][4];
#pragma unroll
        for (int s = 0; s < 2; s++)
#pragma unroll
            for (int nt = 0; nt < 8; nt++) { C[s][nt][0] = C[s][nt][1] = C[s][nt][2] = C[s][nt][3] = 0.f; }

#pragma unroll
        for (int kt = 0; kt < 4; kt++) {
            const int base = 16 * kt + 2 * tig;
            float2 l0 = *(const float2*)(A0 + base), h0 = *(const float2*)(A0 + base + 8);
            float2 l1 = *(const float2*)(A1 + base), h1 = *(const float2*)(A1 + base + 8);
            float2 l2 = *(const float2*)(A2 + base), h2 = *(const float2*)(A2 + base + 8);
            float2 l3 = *(const float2*)(A3 + base), h3 = *(const float2*)(A3 + base + 8);
            uint32_t a00 = pack_h2(l0.x, l0.y), a02 = pack_h2(h0.x, h0.y);
            uint32_t a01 = pack_h2(l1.x, l1.y), a03 = pack_h2(h1.x, h1.y);
            uint32_t a10 = pack_h2(l2.x, l2.y), a12 = pack_h2(h2.x, h2.y);
            uint32_t a11 = pack_h2(l3.x, l3.y), a13 = pack_h2(h3.x, h3.y);
#pragma unroll
            for (int nt = 0; nt < 8; nt++) {
                uint2 b = *(const uint2*)(sWe + (nt * 8 + g) * WSTR + 8 * kt + 2 * tig);
                mma16(C[0][nt], a00, a01, a02, a03, b.x, b.y);
                mma16(C[1][nt], a10, a11, a12, a13, b.x, b.y);
            }
        }

        // ---- gather (f16 tables, pos3: 2x LDG.128 per row per table) + GELU ----
#pragma unroll
        for (int s = 0; s < 4; s++) {
            const int row = rb + 8 * s;
            const int h = s >> 1, pb = (s & 1) * 2;
            const __half* xs = g_xs + (size_t)sSrc[row] * 64 + tig * 16;
            const __half* xt = g_xt + (size_t)sTgt[row] * 64 + tig * 16;
            uint4 pa = *(const uint4*)xs;          // halves 0..7  -> nt 0..3
            uint4 pbv = *(const uint4*)(xs + 8);   // halves 8..15 -> nt 4..7
            uint4 qa = *(const uint4*)xt;
            uint4 qb = *(const uint4*)(xt + 8);
            const __half2* ph = (const __half2*)&pa;
            const __half2* ph2 = (const __half2*)&pbv;
            const __half2* qh = (const __half2*)&qa;
            const __half2* qh2 = (const __half2*)&qb;
#pragma unroll
            for (int i = 0; i < 4; i++) {
                float2 px0 = __half22float2(2 * i < 4 ? ph[2 * i] : ph2[2 * i - 4]);
                float2 px1 = __half22float2(2 * i + 1 < 4 ? ph[2 * i + 1] : ph2[2 * i - 3]);
                float2 qx0 = __half22float2(2 * i < 4 ? qh[2 * i] : qh2[2 * i - 4]);
                float2 qx1 = __half22float2(2 * i + 1 < 4 ? qh[2 * i + 1] : qh2[2 * i - 3]);
                float v0 = C[h][2 * i + 0][pb + 0] + px0.x + qx0.x;
                float v1 = C[h][2 * i + 0][pb + 1] + px0.y + qx0.y;
                float v2 = C[h][2 * i + 1][pb + 0] + px1.x + qx1.x;
                float v3 = C[h][2 * i + 1][pb + 1] + px1.y + qx1.y;
                uint2 w;
                w.x = pack_h2(gelu_tanh(v0), gelu_tanh(v1));
                w.y = pack_h2(gelu_tanh(v2), gelu_tanh(v3));
                *(uint2*)(sEA + row * EAS + 8 * i + 2 * tig) = w;
            }
        }
        __syncwarp();  // H rows are warp-private

        // ---- stage 2: OUT = H @ W1p^T (N permuted) ----
#pragma unroll
        for (int s = 0; s < 2; s++)
#pragma unroll
            for (int nt = 0; nt < 8; nt++) { C[s][nt][0] = C[s][nt][1] = C[s][nt][2] = C[s][nt][3] = 0.f; }

#pragma unroll
        for (int kt = 0; kt < 4; kt++) {
            const int base = 8 * kt + 2 * tig;
            uint2 q0 = *(const uint2*)(A0 + base);
            uint2 q1 = *(const uint2*)(A1 + base);
            uint2 q2 = *(const uint2*)(A2 + base);
            uint2 q3 = *(const uint2*)(A3 + base);
#pragma unroll
            for (int nt = 0; nt < 8; nt++) {
                uint2 b = *(const uint2*)(sW1 + (nt * 8 + g) * WSTR + base);
                mma16(C[0][nt], q0.x, q1.x, q0.y, q1.y, b.x, b.y);
                mma16(C[1][nt], q2.x, q3.x, q2.y, q3.y, b.x, b.y);
            }
        }

        // ---- prefetch next tile's EA ----
        if (tile + WS < NTG) {
            const float* gsrc = ea + (size_t)(tile + WS) * 32 * 64;
#pragma unroll
            for (int i = 0; i < 16; i++) {
                int idx = i * 32 + lane;
                int r = idx >> 4, c4 = (idx & 15) << 2;
                uint32_t dst = eaRowAddr + (uint32_t)(r * EAS + c4) * 4;
                asm volatile("cp.async.cg.shared.global [%0], [%1], 16;"
                             :: "r"(dst), "l"(gsrc + r * 64 + c4) : "memory");
            }
        }
        asm volatile("cp.async.commit_group;" ::: "memory");

        // ---- epilogue: +b1, STG.128 .cs at logical cols i*16 + tig*4 ----
        float4 bia[4];
#pragma unroll
        for (int i = 0; i < 4; i++) bia[i] = *(const float4*)(sB1 + i * 16 + tig * 4);
#pragma unroll
        for (int s = 0; s < 4; s++) {
            const int h = s >> 1, pb = (s & 1) * 2;
            float* orow = out + (size_t)(e0 + g + 8 * s) * 64 + tig * 4;
#pragma unroll
            for (int i = 0; i < 4; i++) {
                float vx = C[h][2 * i + 0][pb + 0] + bia[i].x;
                float vy = C[h][2 * i + 0][pb + 1] + bia[i].y;
                float vz = C[h][2 * i + 1][pb + 0] + bia[i].z;
                float vw = C[h][2 * i + 1][pb + 1] + bia[i].w;
                asm volatile("st.global.cs.v4.f32 [%0], {%1,%2,%3,%4};"
                             :: "l"(orow + i * 16), "f"(vx), "f"(vy), "f"(vz), "f"(vw)
                             : "memory");
            }
        }
    }
}

extern "C" void kernel_launch(void* const* d_in, const int* in_sizes, int n_in,
                              void* d_out, int out_size) {
    const float* x   = (const float*)d_in[0];
    const int*   ei  = (const int*)d_in[1];     // int32 (JAX default x64-disabled)
    const float* ea  = (const float*)d_in[2];
    const float* We  = (const float*)d_in[3];
    const float* be  = (const float*)d_in[4];
    const float* Ws  = (const float*)d_in[5];
    const float* bs  = (const float*)d_in[6];
    const float* Wt  = (const float*)d_in[7];
    const float* bt  = (const float*)d_in[8];
    const float* W1  = (const float*)d_in[9];
    const float* b1  = (const float*)d_in[10];
    float* out = (float*)d_out;

    const size_t smem = (size_t)SMW * 4;   // ~94 KB
    cudaFuncSetAttribute(fused_kernel, cudaFuncAttributeMaxDynamicSharedMemorySize, (int)smem);

    fused_kernel<<<PGRID, 256, smem>>>(x, Ws, bs, Wt, bt, be, ea, ei, We, W1, b1, out);
}

// round 16
// speedup vs baseline: 1.9000x; 1.0744x over previous
#include <cuda_runtime.h>
#include <cuda_fp16.h>
#include <cstdint>
#include <cstddef>

#define NE 1000000
#define NN 50000
#define NTG 31250                      // 32-edge groups (NE divisible by 32)
#define PGRID 296
#define WS (PGRID * 8)                 // total warps
#define NTN (NN / 16)                  // 3125 16-node tiles (exact)

// node projections stored as f16, COLUMN-PERMUTED with pos3:
// logical feature c = 8nt + 2tig + b lives at half-index pos3(c) = 16*tig + 2*nt + b.
__device__ __half g_xs[(size_t)NN * 64];
__device__ __half g_xt[(size_t)NN * 64];
__device__ unsigned int g_bar;         // monotonic device barrier counter

__device__ __forceinline__ uint32_t smem_u32(const void* p) {
    uint32_t a;
    asm("{ .reg .u64 t; cvta.to.shared.u64 t, %1; cvt.u32.u64 %0, t; }" : "=r"(a) : "l"(p));
    return a;
}

__device__ __forceinline__ uint32_t pack_h2(float x, float y) {
    __half2 h = __float22half2_rn(make_float2(x, y));   // lo=x, hi=y
    return *reinterpret_cast<uint32_t*>(&h);
}

// fp16 m16n8k16 with fp32 accumulate
__device__ __forceinline__ void mma16(float c[4],
                                      uint32_t a0, uint32_t a1, uint32_t a2, uint32_t a3,
                                      uint32_t b0, uint32_t b1) {
    asm volatile(
        "mma.sync.aligned.m16n8k16.row.col.f32.f16.f16.f32 "
        "{%0,%1,%2,%3}, {%4,%5,%6,%7}, {%8,%9}, {%10,%11,%12,%13};\n"
        : "=f"(c[0]), "=f"(c[1]), "=f"(c[2]), "=f"(c[3])
        : "r"(a0), "r"(a1), "r"(a2), "r"(a3), "r"(b0), "r"(b1),
          "f"(c[0]), "f"(c[1]), "f"(c[2]), "f"(c[3]));
}

// jax.nn.gelu approximate via MUFU.TANH: 0.5v(1+tanh(0.79788456(v+0.044715v^3)))
__device__ __forceinline__ float gelu_tanh(float v) {
    float u = v * fmaf(0.035677408136300125f, v * v, 0.7978845608028654f);
    float t;
    asm("tanh.approx.f32 %0, %1;" : "=f"(t) : "f"(u));
    float hv = 0.5f * v;
    return fmaf(hv, t, hv);
}

// word map for 16-half chunks: pair p=(c>>1)&7 -> word 8*(c>>4) + 2*(p&3) + (p>>2)

#define K1S 72
#define EAS 72
#define WSTR 40
// smem words: max(phaseA 128*72+128*72 = 18432, phaseB 256*72+2*64*40+512+64+16 = 24144)
#define SMW 24144

__global__ __launch_bounds__(256, 2)
void fused_kernel(const float* __restrict__ x,
                  const float* __restrict__ Ws, const float* __restrict__ bs,
                  const float* __restrict__ Wt, const float* __restrict__ bt,
                  const float* __restrict__ be,
                  const float* __restrict__ ea,
                  const int* __restrict__ eidx,
                  const float* __restrict__ We,
                  const float* __restrict__ W1,
                  const float* __restrict__ b1,
                  float* __restrict__ out) {
    extern __shared__ uint32_t sm[];
    const int tid = threadIdx.x;
    const int warp = tid >> 5, lane = tid & 31, g = lane >> 2, tig = lane & 3;

    // =======================================================================
    // PHASE A: node projections — warp-granular 16-node tiles.
    // Epilogue packs each (row, table) into two STG.128 (pos3 makes each
    // thread's 16 features contiguous) -> fully coalesced table writes.
    // =======================================================================
    {
        uint32_t* sX = sm;                   // 128 x 72 (8 warps x 16 rows)
        uint32_t* sW = sm + 128 * K1S;       // 128 x 72 ([Ws;Wt])

        // stage [Ws;Wt] once per CTA (block-cooperative)
#pragma unroll
        for (int i = 0; i < 16; i++) {
            int idx = i * 256 + tid;
            int table = idx >> 11;
            int rem = idx & 2047;
            int r = rem >> 5, c4 = (rem & 31) * 4;
            const float* W = table ? Wt : Ws;
            float4 v = *(const float4*)(W + r * 128 + c4);
            int p1 = (c4 >> 1) & 7;
            int w1 = ((c4 >> 4) << 3) + 2 * (p1 & 3) + (p1 >> 2);
            int p2 = ((c4 + 2) >> 1) & 7;
            int w2 = (((c4 + 2) >> 4) << 3) + 2 * (p2 & 3) + (p2 >> 2);
            sW[(table * 64 + r) * K1S + w1] = pack_h2(v.x, v.y);
            sW[(table * 64 + r) * K1S + w2] = pack_h2(v.z, v.w);
        }
        __syncthreads();   // weights visible to all warps

        uint32_t* sXw = sX + warp * 16 * K1S;      // this warp's 16-row slice
        const uint32_t* A0 = sXw + g * K1S;
        const uint32_t* A1 = A0 + 8 * K1S;
        const int gw = blockIdx.x * 8 + warp;      // global warp id

        // column word offsets for this lane's float4 (c4 = lane*4)
        const int c4l = lane * 4;
        const int p1l = (c4l >> 1) & 7;
        const int w1l = ((c4l >> 4) << 3) + 2 * (p1l & 3) + (p1l >> 2);
        const int p2l = ((c4l + 2) >> 1) & 7;
        const int w2l = (((c4l + 2) >> 4) << 3) + 2 * (p2l & 3) + (p2l >> 2);

        for (int tile = gw; tile < NTN; tile += WS) {
            const int m0 = tile * 16;
            __syncwarp();    // protect slice from this warp's previous reads
#pragma unroll
            for (int r = 0; r < 16; r++) {
                float4 v = *(const float4*)(x + (size_t)(m0 + r) * 128 + c4l);
                sXw[r * K1S + w1l] = pack_h2(v.x, v.y);
                sXw[r * K1S + w2l] = pack_h2(v.z, v.w);
            }
            __syncwarp();

            float C[16][4];
#pragma unroll
            for (int nt = 0; nt < 16; nt++) { C[nt][0] = C[nt][1] = C[nt][2] = C[nt][3] = 0.f; }

#pragma unroll
            for (int kt = 0; kt < 8; kt++) {
                const int base = 8 * kt + 2 * tig;
                uint2 a0 = *(const uint2*)(A0 + base);   // (a0, a2)
                uint2 a1 = *(const uint2*)(A1 + base);   // (a1, a3)
#pragma unroll
                for (int nt = 0; nt < 16; nt++) {
                    uint2 b = *(const uint2*)(sW + (nt * 8 + g) * K1S + base);
                    mma16(C[nt], a0.x, a1.x, a0.y, a1.y, b.x, b.y);
                }
            }

            const int gr0 = m0 + g;    // rows gr0 and gr0+8 (always in range)
#pragma unroll
            for (int t = 0; t < 2; t++) {
                __half* dst = t ? g_xt : g_xs;
                uint32_t w0[8], w1[8];
#pragma unroll
                for (int ntl = 0; ntl < 8; ntl++) {
                    const int nt = t * 8 + ntl;
                    const int c = ntl * 8 + 2 * tig;           // logical col (b=0)
                    float bias0, bias1;
                    if (t == 0) { bias0 = bs[c] + be[c]; bias1 = bs[c + 1] + be[c + 1]; }
                    else        { bias0 = bt[c];         bias1 = bt[c + 1]; }
                    w0[ntl] = pack_h2(C[nt][0] + bias0, C[nt][1] + bias1);
                    w1[ntl] = pack_h2(C[nt][2] + bias0, C[nt][3] + bias1);
                }
                // row gr0: halves [16tig .. 16tig+15] -> two uint4 stores
                *(uint4*)(dst + (size_t)gr0 * 64 + 16 * tig) =
                    make_uint4(w0[0], w0[1], w0[2], w0[3]);
                *(uint4*)(dst + (size_t)gr0 * 64 + 16 * tig + 8) =
                    make_uint4(w0[4], w0[5], w0[6], w0[7]);
                // row gr0+8
                *(uint4*)(dst + (size_t)(gr0 + 8) * 64 + 16 * tig) =
                    make_uint4(w1[0], w1[1], w1[2], w1[3]);
                *(uint4*)(dst + (size_t)(gr0 + 8) * 64 + 16 * tig + 8) =
                    make_uint4(w1[4], w1[5], w1[6], w1[7]);
            }
        }
    }

    // =======================================================================
    // device-wide barrier (grid == 2 CTAs/SM == fully resident; replay-safe
    // monotonic counter: each launch adds exactly PGRID arrivals)
    // =======================================================================
    __syncthreads();
    if (tid == 0) {
        __threadfence();
        unsigned a;
        asm volatile("atom.global.add.u32 %0, [%1], 1;" : "=r"(a) : "l"(&g_bar) : "memory");
        const unsigned target = (a / PGRID) * PGRID + PGRID;
        unsigned cur;
        do {
            asm volatile("ld.acquire.gpu.u32 %0, [%1];" : "=r"(cur) : "l"(&g_bar) : "memory");
        } while (cur < target);
    }
    __syncthreads();

    // =======================================================================
    // PHASE B: fused edge MLP (R13 pipeline, unchanged)
    // =======================================================================
    uint32_t* sEA = sm;                        // 256 x 72
    uint32_t* sWe = sm + 256 * EAS;            // 64 x 40 (f16x2 words)
    uint32_t* sW1 = sWe + 64 * WSTR;           // 64 x 40
    int* sSrc = (int*)(sW1 + 64 * WSTR);       // 256
    int* sTgt = sSrc + 256;                    // 256
    float* sB1 = (float*)(sTgt + 256);         // 64

    // ---- stage weights ONCE as f16x2 (word map; W1 rows permuted) ----
#pragma unroll
    for (int i = 0; i < 8; i++) {
        int idx = i * 256 + tid;               // 2048 float4 over both tables
        int table = idx >> 10;
        int rem = idx & 1023;
        int r = rem >> 4, c4 = (rem & 15) * 4;
        const float* W = table ? W1 : We;
        uint32_t* dst = table ? sW1 : sWe;
        int rp = table
               ? ((r & 0x31) | ((r & 0x2) << 2) | ((r & 0x8) >> 1) | ((r & 0x4) >> 1))
               : r;
        float4 v = *(const float4*)(W + r * 64 + c4);
        int p1 = (c4 >> 1) & 7;
        int w1 = ((c4 >> 4) << 3) + 2 * (p1 & 3) + (p1 >> 2);
        int p2 = ((c4 + 2) >> 1) & 7;
        int w2 = (((c4 + 2) >> 4) << 3) + 2 * (p2 & 3) + (p2 >> 2);
        dst[rp * WSTR + w1] = pack_h2(v.x, v.y);
        dst[rp * WSTR + w2] = pack_h2(v.z, v.w);
    }
    if (tid < 64) sB1[tid] = b1[tid];
    __syncthreads();   // weights/bias visible; after this, warps are independent

    const int rb = warp * 32 + g;              // row slots: rb, rb+8, rb+16, rb+24
    uint32_t* A0 = sEA + rb * EAS;
    uint32_t* A1 = A0 + 8 * EAS;
    uint32_t* A2 = A0 + 16 * EAS;
    uint32_t* A3 = A0 + 24 * EAS;

    const uint32_t eaRowAddr = smem_u32(sEA) + (uint32_t)(warp * 32) * EAS * 4;
    const int wg0 = blockIdx.x * 8 + warp;     // global warp id

    // ---- prologue: prefetch EA + indices for first tile ----
    int rs = 0, rt = 0;
    if (wg0 < NTG) {
        const float* gsrc = ea + (size_t)wg0 * 32 * 64;
#pragma unroll
        for (int i = 0; i < 16; i++) {
            int idx = i * 32 + lane;
            int r = idx >> 4, c4 = (idx & 15) << 2;
            uint32_t dst = eaRowAddr + (uint32_t)(r * EAS + c4) * 4;
            asm volatile("cp.async.cg.shared.global [%0], [%1], 16;"
                         :: "r"(dst), "l"(gsrc + r * 64 + c4) : "memory");
        }
        rs = eidx[(size_t)wg0 * 32 + lane];
        rt = eidx[NE + (size_t)wg0 * 32 + lane];
    }
    asm volatile("cp.async.commit_group;" ::: "memory");

    for (int tile = wg0; tile < NTG; tile += WS) {
        const long long e0 = (long long)tile * 32;

        sSrc[warp * 32 + lane] = min(max(rs, 0), NN - 1);
        sTgt[warp * 32 + lane] = min(max(rt, 0), NN - 1);
        if (tile + WS < NTG) {
            rs = eidx[(size_t)(tile + WS) * 32 + lane];
            rt = eidx[NE + (size_t)(tile + WS) * 32 + lane];
        }
        asm volatile("cp.async.wait_group 0;" ::: "memory");
        __syncwarp();

        // ---- stage 1: H = EA @ We^T  (f32 pairs -> f16x2 at consumption) ----
        float C[2][8][4];
#pragma unroll
        for (int s = 0; s < 2; s++)
#pragma unroll
            for (int nt = 0; nt < 8; nt++) { C[s][nt][0] = C[s][nt][1] = C[s][nt][2] = C[s][nt][3] = 0.f; }

#pragma unroll
        for (int kt = 0; kt < 4; kt++) {
            const int base = 16 * kt + 2 * tig;
            float2 l0 = *(const float2*)(A0 + base), h0 = *(const float2*)(A0 + base + 8);
            float2 l1 = *(const float2*)(A1 + base), h1 = *(const float2*)(A1 + base + 8);
            float2 l2 = *(const float2*)(A2 + base), h2 = *(const float2*)(A2 + base + 8);
            float2 l3 = *(const float2*)(A3 + base), h3 = *(const float2*)(A3 + base + 8);
            uint32_t a00 = pack_h2(l0.x, l0.y), a02 = pack_h2(h0.x, h0.y);
            uint32_t a01 = pack_h2(l1.x, l1.y), a03 = pack_h2(h1.x, h1.y);
            uint32_t a10 = pack_h2(l2.x, l2.y), a12 = pack_h2(h2.x, h2.y);
            uint32_t a11 = pack_h2(l3.x, l3.y), a13 = pack_h2(h3.x, h3.y);
#pragma unroll
            for (int nt = 0; nt < 8; nt++) {
                uint2 b = *(const uint2*)(sWe + (nt * 8 + g) * WSTR + 8 * kt + 2 * tig);
                mma16(C[0][nt], a00, a01, a02, a03, b.x, b.y);
                mma16(C[1][nt], a10, a11, a12, a13, b.x, b.y);
            }
        }

        // ---- gather (f16 tables, pos3: 2x LDG.128 per row per table) + GELU ----
#pragma unroll
        for (int s = 0; s < 4; s++) {
            const int row = rb + 8 * s;
            const int h = s >> 1, pb = (s & 1) * 2;
            const __half* xs = g_xs + (size_t)sSrc[row] * 64 + tig * 16;
            const __half* xt = g_xt + (size_t)sTgt[row] * 64 + tig * 16;
            uint4 pa = *(const uint4*)xs;          // halves 0..7  -> nt 0..3
            uint4 pbv = *(const uint4*)(xs + 8);   // halves 8..15 -> nt 4..7
            uint4 qa = *(const uint4*)xt;
            uint4 qb = *(const uint4*)(xt + 8);
            const __half2* ph = (const __half2*)&pa;
            const __half2* ph2 = (const __half2*)&pbv;
            const __half2* qh = (const __half2*)&qa;
            const __half2* qh2 = (const __half2*)&qb;
#pragma unroll
            for (int i = 0; i < 4; i++) {
                float2 px0 = __half22float2(2 * i < 4 ? ph[2 * i] : ph2[2 * i - 4]);
                float2 px1 = __half22float2(2 * i + 1 < 4 ? ph[2 * i + 1] : ph2[2 * i - 3]);
                float2 qx0 = __half22float2(2 * i < 4 ? qh[2 * i] : qh2[2 * i - 4]);
                float2 qx1 = __half22float2(2 * i + 1 < 4 ? qh[2 * i + 1] : qh2[2 * i - 3]);
                float v0 = C[h][2 * i + 0][pb + 0] + px0.x + qx0.x;
                float v1 = C[h][2 * i + 0][pb + 1] + px0.y + qx0.y;
                float v2 = C[h][2 * i + 1][pb + 0] + px1.x + qx1.x;
                float v3 = C[h][2 * i + 1][pb + 1] + px1.y + qx1.y;
                uint2 w;
                w.x = pack_h2(gelu_tanh(v0), gelu_tanh(v1));
                w.y = pack_h2(gelu_tanh(v2), gelu_tanh(v3));
                *(uint2*)(sEA + row * EAS + 8 * i + 2 * tig) = w;
            }
        }
        __syncwarp();  // H rows are warp-private

        // ---- stage 2: OUT = H @ W1p^T (N permuted) ----
#pragma unroll
        for (int s = 0; s < 2; s++)
#pragma unroll
            for (int nt = 0; nt < 8; nt++) { C[s][nt][0] = C[s][nt][1] = C[s][nt][2] = C[s][nt][3] = 0.f; }

#pragma unroll
        for (int kt = 0; kt < 4; kt++) {
            const int base = 8 * kt + 2 * tig;
            uint2 q0 = *(const uint2*)(A0 + base);
            uint2 q1 = *(const uint2*)(A1 + base);
            uint2 q2 = *(const uint2*)(A2 + base);
            uint2 q3 = *(const uint2*)(A3 + base);
#pragma unroll
            for (int nt = 0; nt < 8; nt++) {
                uint2 b = *(const uint2*)(sW1 + (nt * 8 + g) * WSTR + base);
                mma16(C[0][nt], q0.x, q1.x, q0.y, q1.y, b.x, b.y);
                mma16(C[1][nt], q2.x, q3.x, q2.y, q3.y, b.x, b.y);
            }
        }

        // ---- prefetch next tile's EA ----
        if (tile + WS < NTG) {
            const float* gsrc = ea + (size_t)(tile + WS) * 32 * 64;
#pragma unroll
            for (int i = 0; i < 16; i++) {
                int idx = i * 32 + lane;
                int r = idx >> 4, c4 = (idx & 15) << 2;
                uint32_t dst = eaRowAddr + (uint32_t)(r * EAS + c4) * 4;
                asm volatile("cp.async.cg.shared.global [%0], [%1], 16;"
                             :: "r"(dst), "l"(gsrc + r * 64 + c4) : "memory");
            }
        }
        asm volatile("cp.async.commit_group;" ::: "memory");

        // ---- epilogue: +b1, STG.128 .cs at logical cols i*16 + tig*4 ----
        float4 bia[4];
#pragma unroll
        for (int i = 0; i < 4; i++) bia[i] = *(const float4*)(sB1 + i * 16 + tig * 4);
#pragma unroll
        for (int s = 0; s < 4; s++) {
            const int h = s >> 1, pb = (s & 1) * 2;
            float* orow = out + (size_t)(e0 + g + 8 * s) * 64 + tig * 4;
#pragma unroll
            for (int i = 0; i < 4; i++) {
                float vx = C[h][2 * i + 0][pb + 0] + bia[i].x;
                float vy = C[h][2 * i + 0][pb + 1] + bia[i].y;
                float vz = C[h][2 * i + 1][pb + 0] + bia[i].z;
                float vw = C[h][2 * i + 1][pb + 1] + bia[i].w;
                asm volatile("st.global.cs.v4.f32 [%0], {%1,%2,%3,%4};"
                             :: "l"(orow + i * 16), "f"(vx), "f"(vy), "f"(vz), "f"(vw)
                             : "memory");
            }
        }
    }
}

extern "C" void kernel_launch(void* const* d_in, const int* in_sizes, int n_in,
                              void* d_out, int out_size) {
    const float* x   = (const float*)d_in[0];
    const int*   ei  = (const int*)d_in[1];     // int32 (JAX default x64-disabled)
    const float* ea  = (const float*)d_in[2];
    const float* We  = (const float*)d_in[3];
    const float* be  = (const float*)d_in[4];
    const float* Ws  = (const float*)d_in[5];
    const float* bs  = (const float*)d_in[6];
    const float* Wt  = (const float*)d_in[7];
    const float* bt  = (const float*)d_in[8];
    const float* W1  = (const float*)d_in[9];
    const float* b1  = (const float*)d_in[10];
    float* out = (float*)d_out;

    const size_t smem = (size_t)SMW * 4;   // ~94 KB
    cudaFuncSetAttribute(fused_kernel, cudaFuncAttributeMaxDynamicSharedMemorySize, (int)smem);

    fused_kernel<<<PGRID, 256, smem>>>(x, Ws, bs, Wt, bt, be, ea, ei, We, W1, b1, out);
}

// round 17
// speedup vs baseline: 1.9368x; 1.0193x over previous
#include <cuda_runtime.h>
#include <cuda_fp16.h>
#include <cstdint>
#include <cstddef>

#define NE 1000000
#define NN 50000
#define NTG 31250                      // 32-edge groups (NE divisible by 32)
#define PGRID 304                      // GB300: 152 SMs x 2 CTAs
#define WS (PGRID * 8)                 // total warps
#define NTN (NN / 16)                  // 3125 16-node tiles (exact)

// node projections stored as f16, COLUMN-PERMUTED with pos3:
// logical feature c = 8nt + 2tig + b lives at half-index pos3(c) = 16*tig + 2*nt + b.
__device__ __half g_xs[(size_t)NN * 64];
__device__ __half g_xt[(size_t)NN * 64];
__device__ unsigned int g_bar;         // monotonic device barrier counter

__device__ __forceinline__ uint32_t smem_u32(const void* p) {
    uint32_t a;
    asm("{ .reg .u64 t; cvta.to.shared.u64 t, %1; cvt.u32.u64 %0, t; }" : "=r"(a) : "l"(p));
    return a;
}

__device__ __forceinline__ uint32_t pack_h2(float x, float y) {
    __half2 h = __float22half2_rn(make_float2(x, y));   // lo=x, hi=y
    return *reinterpret_cast<uint32_t*>(&h);
}

// fp16 m16n8k16 with fp32 accumulate
__device__ __forceinline__ void mma16(float c[4],
                                      uint32_t a0, uint32_t a1, uint32_t a2, uint32_t a3,
                                      uint32_t b0, uint32_t b1) {
    asm volatile(
        "mma.sync.aligned.m16n8k16.row.col.f32.f16.f16.f32 "
        "{%0,%1,%2,%3}, {%4,%5,%6,%7}, {%8,%9}, {%10,%11,%12,%13};\n"
        : "=f"(c[0]), "=f"(c[1]), "=f"(c[2]), "=f"(c[3])
        : "r"(a0), "r"(a1), "r"(a2), "r"(a3), "r"(b0), "r"(b1),
          "f"(c[0]), "f"(c[1]), "f"(c[2]), "f"(c[3]));
}

// jax.nn.gelu approximate via MUFU.TANH: 0.5v(1+tanh(0.79788456(v+0.044715v^3)))
__device__ __forceinline__ float gelu_tanh(float v) {
    float u = v * fmaf(0.035677408136300125f, v * v, 0.7978845608028654f);
    float t;
    asm("tanh.approx.f32 %0, %1;" : "=f"(t) : "f"(u));
    float hv = 0.5f * v;
    return fmaf(hv, t, hv);
}

// word map for 16-half chunks: pair p=(c>>1)&7 -> word 8*(c>>4) + 2*(p&3) + (p>>2)

#define K1S 72
#define EAS 72
#define WSTR 40
// smem words: max(phaseA 128*72+128*72 = 18432, phaseB 256*72+2*64*40+512+64+16 = 24144)
#define SMW 24144

__global__ __launch_bounds__(256, 2)
void fused_kernel(const float* __restrict__ x,
                  const float* __restrict__ Ws, const float* __restrict__ bs,
                  const float* __restrict__ Wt, const float* __restrict__ bt,
                  const float* __restrict__ be,
                  const float* __restrict__ ea,
                  const int* __restrict__ eidx,
                  const float* __restrict__ We,
                  const float* __restrict__ W1,
                  const float* __restrict__ b1,
                  float* __restrict__ out) {
    extern __shared__ uint32_t sm[];
    const int tid = threadIdx.x;
    const int warp = tid >> 5, lane = tid & 31, g = lane >> 2, tig = lane & 3;

    // =======================================================================
    // PHASE A: node projections — warp-granular 16-node tiles.
    // Epilogue packs each (row, table) into two STG.128 (pos3 makes each
    // thread's 16 features contiguous) -> fully coalesced table writes.
    // =======================================================================
    {
        uint32_t* sX = sm;                   // 128 x 72 (8 warps x 16 rows)
        uint32_t* sW = sm + 128 * K1S;       // 128 x 72 ([Ws;Wt])

        // stage [Ws;Wt] once per CTA (block-cooperative)
#pragma unroll
        for (int i = 0; i < 16; i++) {
            int idx = i * 256 + tid;
            int table = idx >> 11;
            int rem = idx & 2047;
            int r = rem >> 5, c4 = (rem & 31) * 4;
            const float* W = table ? Wt : Ws;
            float4 v = *(const float4*)(W + r * 128 + c4);
            int p1 = (c4 >> 1) & 7;
            int w1 = ((c4 >> 4) << 3) + 2 * (p1 & 3) + (p1 >> 2);
            int p2 = ((c4 + 2) >> 1) & 7;
            int w2 = (((c4 + 2) >> 4) << 3) + 2 * (p2 & 3) + (p2 >> 2);
            sW[(table * 64 + r) * K1S + w1] = pack_h2(v.x, v.y);
            sW[(table * 64 + r) * K1S + w2] = pack_h2(v.z, v.w);
        }
        __syncthreads();   // weights visible to all warps

        uint32_t* sXw = sX + warp * 16 * K1S;      // this warp's 16-row slice
        const uint32_t* A0 = sXw + g * K1S;
        const uint32_t* A1 = A0 + 8 * K1S;
        const int gw = blockIdx.x * 8 + warp;      // global warp id

        // column word offsets for this lane's float4 (c4 = lane*4)
        const int c4l = lane * 4;
        const int p1l = (c4l >> 1) & 7;
        const int w1l = ((c4l >> 4) << 3) + 2 * (p1l & 3) + (p1l >> 2);
        const int p2l = ((c4l + 2) >> 1) & 7;
        const int w2l = (((c4l + 2) >> 4) << 3) + 2 * (p2l & 3) + (p2l >> 2);

        for (int tile = gw; tile < NTN; tile += WS) {
            const int m0 = tile * 16;
            __syncwarp();    // protect slice from this warp's previous reads
#pragma unroll
            for (int r = 0; r < 16; r++) {
                float4 v = *(const float4*)(x + (size_t)(m0 + r) * 128 + c4l);
                sXw[r * K1S + w1l] = pack_h2(v.x, v.y);
                sXw[r * K1S + w2l] = pack_h2(v.z, v.w);
            }
            __syncwarp();

            float C[16][4];
#pragma unroll
            for (int nt = 0; nt < 16; nt++) { C[nt][0] = C[nt][1] = C[nt][2] = C[nt][3] = 0.f; }

#pragma unroll
            for (int kt = 0; kt < 8; kt++) {
                const int base = 8 * kt + 2 * tig;
                uint2 a0 = *(const uint2*)(A0 + base);   // (a0, a2)
                uint2 a1 = *(const uint2*)(A1 + base);   // (a1, a3)
#pragma unroll
                for (int nt = 0; nt < 16; nt++) {
                    uint2 b = *(const uint2*)(sW + (nt * 8 + g) * K1S + base);
                    mma16(C[nt], a0.x, a1.x, a0.y, a1.y, b.x, b.y);
                }
            }

            const int gr0 = m0 + g;    // rows gr0 and gr0+8 (always in range)
#pragma unroll
            for (int t = 0; t < 2; t++) {
                __half* dst = t ? g_xt : g_xs;
                uint32_t w0[8], w1[8];
#pragma unroll
                for (int ntl = 0; ntl < 8; ntl++) {
                    const int nt = t * 8 + ntl;
                    const int c = ntl * 8 + 2 * tig;           // logical col (b=0)
                    float bias0, bias1;
                    if (t == 0) { bias0 = bs[c] + be[c]; bias1 = bs[c + 1] + be[c + 1]; }
                    else        { bias0 = bt[c];         bias1 = bt[c + 1]; }
                    w0[ntl] = pack_h2(C[nt][0] + bias0, C[nt][1] + bias1);
                    w1[ntl] = pack_h2(C[nt][2] + bias0, C[nt][3] + bias1);
                }
                // row gr0: halves [16tig .. 16tig+15] -> two uint4 stores
                *(uint4*)(dst + (size_t)gr0 * 64 + 16 * tig) =
                    make_uint4(w0[0], w0[1], w0[2], w0[3]);
                *(uint4*)(dst + (size_t)gr0 * 64 + 16 * tig + 8) =
                    make_uint4(w0[4], w0[5], w0[6], w0[7]);
                // row gr0+8
                *(uint4*)(dst + (size_t)(gr0 + 8) * 64 + 16 * tig) =
                    make_uint4(w1[0], w1[1], w1[2], w1[3]);
                *(uint4*)(dst + (size_t)(gr0 + 8) * 64 + 16 * tig + 8) =
                    make_uint4(w1[4], w1[5], w1[6], w1[7]);
            }
        }
    }

    // =======================================================================
    // device-wide barrier (grid == 2 CTAs/SM on 152 SMs == fully resident;
    // replay-safe monotonic counter: each launch adds exactly PGRID arrivals)
    // =======================================================================
    __syncthreads();
    if (tid == 0) {
        __threadfence();
        unsigned a;
        asm volatile("atom.global.add.u32 %0, [%1], 1;" : "=r"(a) : "l"(&g_bar) : "memory");
        const unsigned target = (a / PGRID) * PGRID + PGRID;
        unsigned cur;
        do {
            asm volatile("ld.acquire.gpu.u32 %0, [%1];" : "=r"(cur) : "l"(&g_bar) : "memory");
        } while (cur < target);
    }
    __syncthreads();

    // =======================================================================
    // PHASE B: fused edge MLP. EA prefetch for tile t+1 is SPLIT: the lanes
    // owning smem words 32..63 (lane&8) issue right after stage 1 (those
    // words are dead once stage-1 A is consumed; H only uses words 0..31);
    // the low-word lanes issue after stage 2 as before.
    // =======================================================================
    uint32_t* sEA = sm;                        // 256 x 72
    uint32_t* sWe = sm + 256 * EAS;            // 64 x 40 (f16x2 words)
    uint32_t* sW1 = sWe + 64 * WSTR;           // 64 x 40
    int* sSrc = (int*)(sW1 + 64 * WSTR);       // 256
    int* sTgt = sSrc + 256;                    // 256
    float* sB1 = (float*)(sTgt + 256);         // 64

    // ---- stage weights ONCE as f16x2 (word map; W1 rows permuted) ----
#pragma unroll
    for (int i = 0; i < 8; i++) {
        int idx = i * 256 + tid;               // 2048 float4 over both tables
        int table = idx >> 10;
        int rem = idx & 1023;
        int r = rem >> 4, c4 = (rem & 15) * 4;
        const float* W = table ? W1 : We;
        uint32_t* dst = table ? sW1 : sWe;
        int rp = table
               ? ((r & 0x31) | ((r & 0x2) << 2) | ((r & 0x8) >> 1) | ((r & 0x4) >> 1))
               : r;
        float4 v = *(const float4*)(W + r * 64 + c4);
        int p1 = (c4 >> 1) & 7;
        int w1 = ((c4 >> 4) << 3) + 2 * (p1 & 3) + (p1 >> 2);
        int p2 = ((c4 + 2) >> 1) & 7;
        int w2 = (((c4 + 2) >> 4) << 3) + 2 * (p2 & 3) + (p2 >> 2);
        dst[rp * WSTR + w1] = pack_h2(v.x, v.y);
        dst[rp * WSTR + w2] = pack_h2(v.z, v.w);
    }
    if (tid < 64) sB1[tid] = b1[tid];
    __syncthreads();   // weights/bias visible; after this, warps are independent

    const int rb = warp * 32 + g;              // row slots: rb, rb+8, rb+16, rb+24
    uint32_t* A0 = sEA + rb * EAS;
    uint32_t* A1 = A0 + 8 * EAS;
    uint32_t* A2 = A0 + 16 * EAS;
    uint32_t* A3 = A0 + 24 * EAS;

    const uint32_t eaRowAddr = smem_u32(sEA) + (uint32_t)(warp * 32) * EAS * 4;
    const int wg0 = blockIdx.x * 8 + warp;     // global warp id
    const int hiLane = (lane & 8);             // lanes owning column chunks 32..63

    // ---- prologue: prefetch EA + indices for first tile ----
    int rs = 0, rt = 0;
    if (wg0 < NTG) {
        const float* gsrc = ea + (size_t)wg0 * 32 * 64;
#pragma unroll
        for (int i = 0; i < 16; i++) {
            int idx = i * 32 + lane;
            int r = idx >> 4, c4 = (idx & 15) << 2;
            uint32_t dst = eaRowAddr + (uint32_t)(r * EAS + c4) * 4;
            asm volatile("cp.async.cg.shared.global [%0], [%1], 16;"
                         :: "r"(dst), "l"(gsrc + r * 64 + c4) : "memory");
        }
        rs = eidx[(size_t)wg0 * 32 + lane];
        rt = eidx[NE + (size_t)wg0 * 32 + lane];
    }
    asm volatile("cp.async.commit_group;" ::: "memory");

    for (int tile = wg0; tile < NTG; tile += WS) {
        const long long e0 = (long long)tile * 32;

        sSrc[warp * 32 + lane] = min(max(rs, 0), NN - 1);
        sTgt[warp * 32 + lane] = min(max(rt, 0), NN - 1);
        if (tile + WS < NTG) {
            rs = eidx[(size_t)(tile + WS) * 32 + lane];
            rt = eidx[NE + (size_t)(tile + WS) * 32 + lane];
        }
        asm volatile("cp.async.wait_group 0;" ::: "memory");
        __syncwarp();

        // ---- stage 1: H = EA @ We^T  (f32 pairs -> f16x2 at consumption) ----
        float C[2][8][4];
#pragma unroll
        for (int s = 0; s < 2; s++)
#pragma unroll
            for (int nt = 0; nt < 8; nt++) { C[s][nt][0] = C[s][nt][1] = C[s][nt][2] = C[s][nt][3] = 0.f; }

#pragma unroll
        for (int kt = 0; kt < 4; kt++) {
            const int base = 16 * kt + 2 * tig;
            float2 l0 = *(const float2*)(A0 + base), h0 = *(const float2*)(A0 + base + 8);
            float2 l1 = *(const float2*)(A1 + base), h1 = *(const float2*)(A1 + base + 8);
            float2 l2 = *(const float2*)(A2 + base), h2 = *(const float2*)(A2 + base + 8);
            float2 l3 = *(const float2*)(A3 + base), h3 = *(const float2*)(A3 + base + 8);
            uint32_t a00 = pack_h2(l0.x, l0.y), a02 = pack_h2(h0.x, h0.y);
            uint32_t a01 = pack_h2(l1.x, l1.y), a03 = pack_h2(h1.x, h1.y);
            uint32_t a10 = pack_h2(l2.x, l2.y), a12 = pack_h2(h2.x, h2.y);
            uint32_t a11 = pack_h2(l3.x, l3.y), a13 = pack_h2(h3.x, h3.y);
#pragma unroll
            for (int nt = 0; nt < 8; nt++) {
                uint2 b = *(const uint2*)(sWe + (nt * 8 + g) * WSTR + 8 * kt + 2 * tig);
                mma16(C[0][nt], a00, a01, a02, a03, b.x, b.y);
                mma16(C[1][nt], a10, a11, a12, a13, b.x, b.y);
            }
        }

        // ---- EARLY half-prefetch of next tile's EA (words 32..63 are dead) ----
        if (tile + WS < NTG && hiLane) {
            const float* gsrc = ea + (size_t)(tile + WS) * 32 * 64;
#pragma unroll
            for (int i = 0; i < 16; i++) {
                int idx = i * 32 + lane;
                int r = idx >> 4, c4 = (idx & 15) << 2;   // c4 in 32..60 for hi lanes
                uint32_t dst = eaRowAddr + (uint32_t)(r * EAS + c4) * 4;
                asm volatile("cp.async.cg.shared.global [%0], [%1], 16;"
                             :: "r"(dst), "l"(gsrc + r * 64 + c4) : "memory");
            }
        }
        asm volatile("cp.async.commit_group;" ::: "memory");

        // ---- gather (f16 tables, pos3: 2x LDG.128 per row per table) + GELU ----
#pragma unroll
        for (int s = 0; s < 4; s++) {
            const int row = rb + 8 * s;
            const int h = s >> 1, pb = (s & 1) * 2;
            const __half* xs = g_xs + (size_t)sSrc[row] * 64 + tig * 16;
            const __half* xt = g_xt + (size_t)sTgt[row] * 64 + tig * 16;
            uint4 pa = *(const uint4*)xs;          // halves 0..7  -> nt 0..3
            uint4 pbv = *(const uint4*)(xs + 8);   // halves 8..15 -> nt 4..7
            uint4 qa = *(const uint4*)xt;
            uint4 qb = *(const uint4*)(xt + 8);
            const __half2* ph = (const __half2*)&pa;
            const __half2* ph2 = (const __half2*)&pbv;
            const __half2* qh = (const __half2*)&qa;
            const __half2* qh2 = (const __half2*)&qb;
#pragma unroll
            for (int i = 0; i < 4; i++) {
                float2 px0 = __half22float2(2 * i < 4 ? ph[2 * i] : ph2[2 * i - 4]);
                float2 px1 = __half22float2(2 * i + 1 < 4 ? ph[2 * i + 1] : ph2[2 * i - 3]);
                float2 qx0 = __half22float2(2 * i < 4 ? qh[2 * i] : qh2[2 * i - 4]);
                float2 qx1 = __half22float2(2 * i + 1 < 4 ? qh[2 * i + 1] : qh2[2 * i - 3]);
                float v0 = C[h][2 * i + 0][pb + 0] + px0.x + qx0.x;
                float v1 = C[h][2 * i + 0][pb + 1] + px0.y + qx0.y;
                float v2 = C[h][2 * i + 1][pb + 0] + px1.x + qx1.x;
                float v3 = C[h][2 * i + 1][pb + 1] + px1.y + qx1.y;
                uint2 w;
                w.x = pack_h2(gelu_tanh(v0), gelu_tanh(v1));
                w.y = pack_h2(gelu_tanh(v2), gelu_tanh(v3));
                *(uint2*)(sEA + row * EAS + 8 * i + 2 * tig) = w;
            }
        }
        __syncwarp();  // H rows are warp-private

        // ---- stage 2: OUT = H @ W1p^T (N permuted) ----
#pragma unroll
        for (int s = 0; s < 2; s++)
#pragma unroll
            for (int nt = 0; nt < 8; nt++) { C[s][nt][0] = C[s][nt][1] = C[s][nt][2] = C[s][nt][3] = 0.f; }

#pragma unroll
        for (int kt = 0; kt < 4; kt++) {
            const int base = 8 * kt + 2 * tig;
            uint2 q0 = *(const uint2*)(A0 + base);
            uint2 q1 = *(const uint2*)(A1 + base);
            uint2 q2 = *(const uint2*)(A2 + base);
            uint2 q3 = *(const uint2*)(A3 + base);
#pragma unroll
            for (int nt = 0; nt < 8; nt++) {
                uint2 b = *(const uint2*)(sW1 + (nt * 8 + g) * WSTR + base);
                mma16(C[0][nt], q0.x, q1.x, q0.y, q1.y, b.x, b.y);
                mma16(C[1][nt], q2.x, q3.x, q2.y, q3.y, b.x, b.y);
            }
        }

        // ---- LATE half-prefetch of next tile's EA (words 0..31, H consumed) ----
        if (tile + WS < NTG && !hiLane) {
            const float* gsrc = ea + (size_t)(tile + WS) * 32 * 64;
#pragma unroll
            for (int i = 0; i < 16; i++) {
                int idx = i * 32 + lane;
                int r = idx >> 4, c4 = (idx & 15) << 2;   // c4 in 0..28 for lo lanes
                uint32_t dst = eaRowAddr + (uint32_t)(r * EAS + c4) * 4;
                asm volatile("cp.async.cg.shared.global [%0], [%1], 16;"
                             :: "r"(dst), "l"(gsrc + r * 64 + c4) : "memory");
            }
        }
        asm volatile("cp.async.commit_group;" ::: "memory");

        // ---- epilogue: +b1, STG.128 .cs at logical cols i*16 + tig*4 ----
        float4 bia[4];
#pragma unroll
        for (int i = 0; i < 4; i++) bia[i] = *(const float4*)(sB1 + i * 16 + tig * 4);
#pragma unroll
        for (int s = 0; s < 4; s++) {
            const int h = s >> 1, pb = (s & 1) * 2;
            float* orow = out + (size_t)(e0 + g + 8 * s) * 64 + tig * 4;
#pragma unroll
            for (int i = 0; i < 4; i++) {
                float vx = C[h][2 * i + 0][pb + 0] + bia[i].x;
                float vy = C[h][2 * i + 0][pb + 1] + bia[i].y;
                float vz = C[h][2 * i + 1][pb + 0] + bia[i].z;
                float vw = C[h][2 * i + 1][pb + 1] + bia[i].w;
                asm volatile("st.global.cs.v4.f32 [%0], {%1,%2,%3,%4};"
                             :: "l"(orow + i * 16), "f"(vx), "f"(vy), "f"(vz), "f"(vw)
                             : "memory");
            }
        }
    }
}

extern "C" void kernel_launch(void* const* d_in, const int* in_sizes, int n_in,
                              void* d_out, int out_size) {
    const float* x   = (const float*)d_in[0];
    const int*   ei  = (const int*)d_in[1];     // int32 (JAX default x64-disabled)
    const float* ea  = (const float*)d_in[2];
    const float* We  = (const float*)d_in[3];
    const float* be  = (const float*)d_in[4];
    const float* Ws  = (const float*)d_in[5];
    const float* bs  = (const float*)d_in[6];
    const float* Wt  = (const float*)d_in[7];
    const float* bt  = (const float*)d_in[8];
    const float* W1  = (const float*)d_in[9];
    const float* b1  = (const float*)d_in[10];
    float* out = (float*)d_out;

    const size_t smem = (size_t)SMW * 4;   // ~94 KB
    cudaFuncSetAttribute(fused_kernel, cudaFuncAttributeMaxDynamicSharedMemorySize, (int)smem);

    fused_kernel<<<PGRID, 256, smem>>>(x, Ws, bs, Wt, bt, be, ea, ei, We, W1, b1, out);
}